// round 3
// baseline (speedup 1.0000x reference)
#include <cuda_runtime.h>
#include <math.h>

// ---------------- problem constants ----------------
#define BSZ    2
#define LSEQ   4096
#define DMODEL 1024
#define DIEXP  2048          // DI
#define NH     32
#define HP     64
#define DS     128           // state dim (NG=1)
#define CS     64            // chunk size
#define NC     64            // LSEQ / CS
#define DPROJ  4384          // 2*DI + 2*DS + NH
#define CONVD  2304          // DI + 2*DS
#define ROWS   8192          // BSZ * LSEQ

// ---------------- device scratch (no runtime alloc allowed) ----------------
__device__ float g_zxbcdt[(size_t)ROWS * DPROJ];          // ~143.6 MB
__device__ float g_xconv [(size_t)ROWS * CONVD];          // ~75.5 MB
__device__ float g_dt    [ROWS * NH];
__device__ float g_adt   [ROWS * NH];
__device__ float g_CB    [BSZ * NC * CS * CS];            // 2 MB
__device__ float g_states[(size_t)BSZ * NC * NH * HP * DS]; // 134 MB (in-place -> states_in)
__device__ float g_dchunk[BSZ * NC * NH];
__device__ float g_y     [(size_t)ROWS * DIEXP];          // 67 MB

// ---------------- generic fp32 SGEMM: C = A(MxK) @ B(KxN), row major --------
// 128x128 block tile, BK=8, 256 threads, 8x8 per thread. M assumed %128==0.
__global__ __launch_bounds__(256) void sgemm_kernel(
    const float* __restrict__ A, const float* __restrict__ B,
    float* __restrict__ C, int M, int N, int K)
{
    __shared__ float As[8][128];
    __shared__ float Bs[8][128];

    const int tid  = threadIdx.x;
    const int tx   = tid & 15;        // n sub-tile
    const int ty   = tid >> 4;        // m sub-tile
    const int mBase = blockIdx.y * 128;
    const int nBase = blockIdx.x * 128;

    const int rowA = tid >> 1;          // 0..127
    const int colA = (tid & 1) * 4;     // 0 or 4
    const int rowB = tid >> 5;          // 0..7
    const int colB = (tid & 31) * 4;    // 0..124

    float acc[8][8];
    #pragma unroll
    for (int i = 0; i < 8; ++i)
        #pragma unroll
        for (int j = 0; j < 8; ++j) acc[i][j] = 0.f;

    for (int k0 = 0; k0 < K; k0 += 8) {
        // A tile (transpose into As[k][m]); K % 4 == 0 so float4 ok
        float4 av = *(const float4*)&A[(size_t)(mBase + rowA) * K + k0 + colA];
        As[colA + 0][rowA] = av.x;
        As[colA + 1][rowA] = av.y;
        As[colA + 2][rowA] = av.z;
        As[colA + 3][rowA] = av.w;
        // B tile (guard right edge)
        #pragma unroll
        for (int i = 0; i < 4; ++i) {
            int n = nBase + colB + i;
            Bs[rowB][colB + i] = (n < N) ? B[(size_t)(k0 + rowB) * N + n] : 0.f;
        }
        __syncthreads();

        #pragma unroll
        for (int kk = 0; kk < 8; ++kk) {
            float ar[8], br[8];
            *(float4*)(ar)     = *(const float4*)&As[kk][ty * 8];
            *(float4*)(ar + 4) = *(const float4*)&As[kk][ty * 8 + 4];
            *(float4*)(br)     = *(const float4*)&Bs[kk][tx * 8];
            *(float4*)(br + 4) = *(const float4*)&Bs[kk][tx * 8 + 4];
            #pragma unroll
            for (int i = 0; i < 8; ++i)
                #pragma unroll
                for (int j = 0; j < 8; ++j)
                    acc[i][j] = fmaf(ar[i], br[j], acc[i][j]);
        }
        __syncthreads();
    }

    #pragma unroll
    for (int i = 0; i < 8; ++i) {
        int m = mBase + ty * 8 + i;
        #pragma unroll
        for (int j = 0; j < 8; ++j) {
            int n = nBase + tx * 8 + j;
            if (n < N) C[(size_t)m * N + n] = acc[i][j];
        }
    }
}

// ---------------- causal depthwise conv (k=4) + SiLU ----------------
__global__ __launch_bounds__(256) void conv_silu_kernel(
    const float* __restrict__ conv_w, const float* __restrict__ conv_b)
{
    int idx = blockIdx.x * 256 + threadIdx.x;
    if (idx >= ROWS * CONVD) return;
    int r = idx / CONVD;
    int c = idx - r * CONVD;
    int l = r & (LSEQ - 1);

    float acc = conv_b[c];
    #pragma unroll
    for (int i = 0; i < 4; ++i) {
        int ll = l - 3 + i;
        if (ll >= 0)
            acc = fmaf(g_zxbcdt[(size_t)(r - 3 + i) * DPROJ + DIEXP + c],
                       conv_w[c * 4 + i], acc);
    }
    // silu
    float s = acc / (1.f + expf(-acc));
    g_xconv[(size_t)r * CONVD + c] = s;
}

// ---------------- dt = softplus(raw + bias), adt = A * dt ----------------
__global__ __launch_bounds__(256) void dt_kernel(
    const float* __restrict__ dt_bias, const float* __restrict__ A_log)
{
    int idx = blockIdx.x * 256 + threadIdx.x;
    if (idx >= ROWS * NH) return;
    int r = idx >> 5;
    int h = idx & 31;
    float x = g_zxbcdt[(size_t)r * DPROJ + (DPROJ - NH) + h] + dt_bias[h];
    float sp = (x > 20.f) ? x : log1pf(expf(x));
    g_dt[idx]  = sp;
    g_adt[idx] = -expf(A_log[h]) * sp;
}

// ---------------- CB[b,c,i,j] = sum_n C[i,n] * B[j,n]  (NG=1: head-indep) ---
__global__ __launch_bounds__(256) void cb_kernel()
{
    __shared__ float Cs[64][65];
    __shared__ float Bs[64][65];
    const int bc = blockIdx.x;           // b*NC + c ; global row base = bc*64
    const int rowBase = bc * CS;
    const int tid = threadIdx.x;
    const int tx = tid & 15, ty = tid >> 4;

    float acc[4][4];
    #pragma unroll
    for (int a = 0; a < 4; ++a)
        #pragma unroll
        for (int b2 = 0; b2 < 4; ++b2) acc[a][b2] = 0.f;

    for (int n0 = 0; n0 < DS; n0 += 64) {
        for (int t = tid; t < 4096; t += 256) {
            int i = t >> 6, n = t & 63;
            const size_t row = (size_t)(rowBase + i) * CONVD;
            Cs[i][n] = g_xconv[row + DIEXP + DS + n0 + n];
            Bs[i][n] = g_xconv[row + DIEXP + n0 + n];
        }
        __syncthreads();
        for (int n = 0; n < 64; ++n) {
            float cr[4], br[4];
            #pragma unroll
            for (int a = 0; a < 4; ++a)  cr[a]  = Cs[ty * 4 + a][n];
            #pragma unroll
            for (int b2 = 0; b2 < 4; ++b2) br[b2] = Bs[tx * 4 + b2][n];
            #pragma unroll
            for (int a = 0; a < 4; ++a)
                #pragma unroll
                for (int b2 = 0; b2 < 4; ++b2)
                    acc[a][b2] = fmaf(cr[a], br[b2], acc[a][b2]);
        }
        __syncthreads();
    }
    #pragma unroll
    for (int a = 0; a < 4; ++a)
        #pragma unroll
        for (int b2 = 0; b2 < 4; ++b2)
            g_CB[bc * 4096 + (ty * 4 + a) * 64 + tx * 4 + b2] = acc[a][b2];
}

// ---------------- per-chunk states[p,n] = sum_s x*dt*decay * B ---------------
__global__ __launch_bounds__(256) void states_kernel()
{
    const int c = blockIdx.x, b = blockIdx.y, h = blockIdx.z;
    const int tid = threadIdx.x;
    const int tx = tid & 15, ty = tid >> 4;
    const int rowBase = b * LSEQ + c * CS;

    __shared__ float a_s[CS];
    __shared__ float acum[CS];
    __shared__ float xw[CS][64];
    __shared__ float Bs[CS][64];

    if (tid < CS) a_s[tid] = g_adt[(rowBase + tid) * NH + h];
    __syncthreads();
    if (tid == 0) {
        float s = 0.f;
        #pragma unroll
        for (int i = 0; i < CS; ++i) { s += a_s[i]; acum[i] = s; }
        g_dchunk[(b * NC + c) * NH + h] = expf(s);
    }
    __syncthreads();

    const float aend = acum[CS - 1];
    for (int t = tid; t < CS * 64; t += 256) {
        int s = t >> 6, p = t & 63;
        float w = expf(aend - acum[s]);
        xw[s][p] = g_xconv[(size_t)(rowBase + s) * CONVD + h * HP + p]
                   * g_dt[(rowBase + s) * NH + h] * w;
    }

    const size_t obase = ((size_t)((b * NC + c) * NH + h)) * (HP * DS);
    for (int n0 = 0; n0 < DS; n0 += 64) {
        for (int t = tid; t < CS * 64; t += 256) {
            int s = t >> 6, n = t & 63;
            Bs[s][n] = g_xconv[(size_t)(rowBase + s) * CONVD + DIEXP + n0 + n];
        }
        __syncthreads();
        float acc[4][4];
        #pragma unroll
        for (int a = 0; a < 4; ++a)
            #pragma unroll
            for (int b2 = 0; b2 < 4; ++b2) acc[a][b2] = 0.f;
        for (int s = 0; s < CS; ++s) {
            float xr[4], br[4];
            #pragma unroll
            for (int a = 0; a < 4; ++a)  xr[a]  = xw[s][ty * 4 + a];
            #pragma unroll
            for (int b2 = 0; b2 < 4; ++b2) br[b2] = Bs[s][tx * 4 + b2];
            #pragma unroll
            for (int a = 0; a < 4; ++a)
                #pragma unroll
                for (int b2 = 0; b2 < 4; ++b2)
                    acc[a][b2] = fmaf(xr[a], br[b2], acc[a][b2]);
        }
        #pragma unroll
        for (int a = 0; a < 4; ++a)
            #pragma unroll
            for (int b2 = 0; b2 < 4; ++b2)
                g_states[obase + (size_t)(ty * 4 + a) * DS + n0 + tx * 4 + b2] = acc[a][b2];
        __syncthreads();
    }
}

// ---------------- inter-chunk recurrence (in place: states -> states_in) -----
// states_in[c+1] = states[c] + exp(dA[c]) * states_in[c]   (NOTE: the fresh
// chunk state is NOT multiplied by its own chunk decay — decay_chunk[z,z]=1)
__global__ __launch_bounds__(256) void recur_kernel()
{
    const int b = blockIdx.x, h = blockIdx.y;
    const int tid = threadIdx.x;
    float S[32];
    #pragma unroll
    for (int e = 0; e < 32; ++e) S[e] = 0.f;

    for (int c = 0; c < NC; ++c) {
        float d = g_dchunk[(b * NC + c) * NH + h];
        size_t base = ((size_t)((b * NC + c) * NH + h)) * (HP * DS);
        #pragma unroll
        for (int e = 0; e < 32; ++e) {
            size_t idx = base + e * 256 + tid;
            float t = g_states[idx];
            g_states[idx] = S[e];              // states_in for chunk c
            S[e] = fmaf(d, S[e], t);           // t + d * S  (FIXED)
        }
    }
}

// ---------------- Y = Y_off + Y_diag per (b,c,h) -----------------------------
__global__ __launch_bounds__(256) void y_kernel()
{
    const int c = blockIdx.x, b = blockIdx.y, h = blockIdx.z;
    const int tid = threadIdx.x;
    const int tx = tid & 15, ty = tid >> 4;   // ty -> i (seq), tx -> p (head dim)
    const int rowBase = b * LSEQ + c * CS;

    __shared__ float a_s[CS];
    __shared__ float acum[CS];
    __shared__ float sA[CS][65];
    __shared__ float sB[CS][65];

    if (tid < CS) a_s[tid] = g_adt[(rowBase + tid) * NH + h];
    __syncthreads();
    if (tid == 0) {
        float s = 0.f;
        #pragma unroll
        for (int i = 0; i < CS; ++i) { s += a_s[i]; acum[i] = s; }
    }
    __syncthreads();

    float acc[4][4];
    #pragma unroll
    for (int a = 0; a < 4; ++a)
        #pragma unroll
        for (int b2 = 0; b2 < 4; ++b2) acc[a][b2] = 0.f;

    // ---- Phase A: Yoff[i,p] = exp(acum[i]) * sum_n C[i,n] * Sin[p,n] ----
    const size_t sbase = ((size_t)((b * NC + c) * NH + h)) * (HP * DS);
    for (int n0 = 0; n0 < DS; n0 += 64) {
        for (int t = tid; t < 4096; t += 256) {
            int i = t >> 6, n = t & 63;
            sA[i][n] = g_xconv[(size_t)(rowBase + i) * CONVD + DIEXP + DS + n0 + n]; // C[i,n]
            sB[i][n] = g_states[sbase + (size_t)i * DS + n0 + n];                    // Sin[p=i,n]
        }
        __syncthreads();
        for (int n = 0; n < 64; ++n) {
            float cr[4], sr[4];
            #pragma unroll
            for (int a = 0; a < 4; ++a)  cr[a]  = sA[ty * 4 + a][n];
            #pragma unroll
            for (int b2 = 0; b2 < 4; ++b2) sr[b2] = sB[tx * 4 + b2][n];
            #pragma unroll
            for (int a = 0; a < 4; ++a)
                #pragma unroll
                for (int b2 = 0; b2 < 4; ++b2)
                    acc[a][b2] = fmaf(cr[a], sr[b2], acc[a][b2]);
        }
        __syncthreads();
    }
    #pragma unroll
    for (int a = 0; a < 4; ++a) {
        float ei = expf(acum[ty * 4 + a]);
        #pragma unroll
        for (int b2 = 0; b2 < 4; ++b2) acc[a][b2] *= ei;
    }

    // ---- Phase B: Yd[i,p] = sum_{j<=i} CB[i,j]*exp(acum[i]-acum[j]) * xdt[j,p]
    // Build W in shared cooperatively (4096 exps/block, not 64K/thread-redundant)
    const int cbBase = (b * NC + c) * 4096;
    for (int t = tid; t < 4096; t += 256) {
        int i = t >> 6, jj = t & 63;
        float w = 0.f;
        if (jj <= i) w = g_CB[cbBase + i * 64 + jj] * expf(acum[i] - acum[jj]);
        sA[i][jj] = w;                                          // W[i,j]
        // xdt[j,p]: reuse (i->j, jj->p)
        sB[i][jj] = g_xconv[(size_t)(rowBase + i) * CONVD + h * HP + jj]
                    * g_dt[(rowBase + i) * NH + h];
    }
    __syncthreads();
    for (int j = 0; j < 64; ++j) {
        float wr[4], xr[4];
        #pragma unroll
        for (int a = 0; a < 4; ++a)  wr[a]  = sA[ty * 4 + a][j];
        #pragma unroll
        for (int b2 = 0; b2 < 4; ++b2) xr[b2] = sB[j][tx * 4 + b2];
        #pragma unroll
        for (int a = 0; a < 4; ++a)
            #pragma unroll
            for (int b2 = 0; b2 < 4; ++b2)
                acc[a][b2] = fmaf(wr[a], xr[b2], acc[a][b2]);
    }

    #pragma unroll
    for (int a = 0; a < 4; ++a)
        #pragma unroll
        for (int b2 = 0; b2 < 4; ++b2)
            g_y[(size_t)(rowBase + ty * 4 + a) * DIEXP + h * HP + tx * 4 + b2]
                = acc[a][b2];
}

// ---------------- gate (y * silu(z)) + LayerNorm -----------------------------
__global__ __launch_bounds__(256) void gatenorm_kernel(
    const float* __restrict__ norm_w, const float* __restrict__ norm_b)
{
    const int r = blockIdx.x;
    const int tid = threadIdx.x;
    __shared__ float red[256];

    float v[8];
    float lsum = 0.f;
    #pragma unroll
    for (int e = 0; e < 8; ++e) {
        int col = e * 256 + tid;
        float z  = g_zxbcdt[(size_t)r * DPROJ + col];
        float yv = g_y[(size_t)r * DIEXP + col];
        float val = yv * (z / (1.f + expf(-z)));
        v[e] = val;
        lsum += val;
    }
    red[tid] = lsum;
    __syncthreads();
    for (int o = 128; o > 0; o >>= 1) {
        if (tid < o) red[tid] += red[tid + o];
        __syncthreads();
    }
    float mu = red[0] / (float)DIEXP;
    __syncthreads();

    float ls2 = 0.f;
    #pragma unroll
    for (int e = 0; e < 8; ++e) { float d = v[e] - mu; ls2 = fmaf(d, d, ls2); }
    red[tid] = ls2;
    __syncthreads();
    for (int o = 128; o > 0; o >>= 1) {
        if (tid < o) red[tid] += red[tid + o];
        __syncthreads();
    }
    float rstd = rsqrtf(red[0] / (float)DIEXP + 1e-5f);

    #pragma unroll
    for (int e = 0; e < 8; ++e) {
        int col = e * 256 + tid;
        g_y[(size_t)r * DIEXP + col] = (v[e] - mu) * rstd * norm_w[col] + norm_b[col];
    }
}

// ---------------- launch -----------------------------------------------------
extern "C" void kernel_launch(void* const* d_in, const int* in_sizes, int n_in,
                              void* d_out, int out_size)
{
    const float* u       = (const float*)d_in[0];
    const float* W_in    = (const float*)d_in[1];
    const float* conv_w  = (const float*)d_in[2];
    const float* conv_b  = (const float*)d_in[3];
    const float* dt_bias = (const float*)d_in[4];
    const float* A_log   = (const float*)d_in[5];
    const float* norm_w  = (const float*)d_in[6];
    const float* norm_b  = (const float*)d_in[7];
    const float* W_out   = (const float*)d_in[8];
    float* out = (float*)d_out;

    float *zx = nullptr, *yb = nullptr;
    cudaGetSymbolAddress((void**)&zx, g_zxbcdt);
    cudaGetSymbolAddress((void**)&yb, g_y);

    // 1) zxbcdt = u @ W_in    (8192 x 4384, K=1024)
    sgemm_kernel<<<dim3((DPROJ + 127) / 128, ROWS / 128), 256>>>(
        u, W_in, zx, ROWS, DPROJ, DMODEL);
    // 2) causal dwconv + silu
    conv_silu_kernel<<<(ROWS * CONVD + 255) / 256, 256>>>(conv_w, conv_b);
    // 3) dt / A*dt
    dt_kernel<<<(ROWS * NH + 255) / 256, 256>>>(dt_bias, A_log);
    // 4) CB gram matrices per (b, chunk)
    cb_kernel<<<BSZ * NC, 256>>>();
    // 5) per-chunk states
    states_kernel<<<dim3(NC, BSZ, NH), 256>>>();
    // 6) inter-chunk recurrence (states -> states_in in place)
    recur_kernel<<<dim3(BSZ, NH), 256>>>();
    // 7) Y = Yd + Yoff
    y_kernel<<<dim3(NC, BSZ, NH), 256>>>();
    // 8) gate + layernorm
    gatenorm_kernel<<<ROWS, 256>>>(norm_w, norm_b);
    // 9) out = y @ W_out      (8192 x 1024, K=2048)
    sgemm_kernel<<<dim3(DMODEL / 128, ROWS / 128), 256>>>(
        yb, W_out, out, ROWS, DMODEL, DIEXP);
}

// round 4
// speedup vs baseline: 2.3002x; 2.3002x over previous
#include <cuda_runtime.h>
#include <math.h>
#include <stdint.h>

// ---------------- problem constants ----------------
#define BSZ    2
#define LSEQ   4096
#define DMODEL 1024
#define DIEXP  2048          // DI
#define NH     32
#define HP     64
#define DS     128           // state dim (NG=1)
#define CS     64            // chunk size
#define NC     64            // LSEQ / CS
#define DPROJ  4384          // 2*DI + 2*DS + NH
#define CONVD  2304          // DI + 2*DS
#define ROWS   8192          // BSZ * LSEQ

// ---------------- device scratch (no runtime alloc allowed) ----------------
__device__ float g_zxbcdt[(size_t)ROWS * DPROJ];
__device__ float g_xconv [(size_t)ROWS * CONVD];
__device__ float g_dt    [ROWS * NH];
__device__ float g_adt   [ROWS * NH];
__device__ float g_CB    [BSZ * NC * CS * CS];
__device__ float g_states[(size_t)BSZ * NC * NH * HP * DS];
__device__ float g_dchunk[BSZ * NC * NH];
__device__ float g_y     [(size_t)ROWS * DIEXP];

// =====================================================================
// TF32 tensor-core GEMM: C = A(MxK) @ B(KxN), row-major fp32 in/out.
// Block tile 128x128, BK=16, 256 threads (8 warps, 4x2), warp tile 32x64.
// mma.sync.aligned.m16n8k8 tf32. Double-buffered smem.
// M % 128 == 0, K % 16 == 0; N edge guarded.
// =====================================================================
__device__ __forceinline__ uint32_t f2tf32(float x) {
    uint32_t r;
    asm("cvt.rna.tf32.f32 %0, %1;" : "=r"(r) : "f"(x));
    return r;
}

#define AS_STRIDE 20
#define BS_STRIDE 136

__global__ __launch_bounds__(256) void gemm_tf32_kernel(
    const float* __restrict__ A, const float* __restrict__ B,
    float* __restrict__ C, int M, int N, int K)
{
    __shared__ uint32_t As[2][128 * AS_STRIDE];   // [m][k], tf32 bits
    __shared__ uint32_t Bs[2][16 * BS_STRIDE];    // [k][n], tf32 bits

    const int tid   = threadIdx.x;
    const int wid   = tid >> 5;
    const int lane  = tid & 31;
    const int gid   = lane >> 2;       // group id 0..7
    const int tig   = lane & 3;        // thread-in-group 0..3
    const int wm    = wid >> 1;        // 0..3
    const int wn    = wid & 1;         // 0..1
    const int mBase = blockIdx.y * 128;
    const int nBase = blockIdx.x * 128;
    const bool fullN = (nBase + 128 <= N);

    // A stage-load indices: 512 float4 per stage
    const int aRow0 = tid >> 1;                 // with i: f4id = tid + i*256 -> row = f4id>>2
    // B: f4id = tid + i*256 -> row = f4id>>5, c4 = f4id&31

    float acc[2][8][4];
    #pragma unroll
    for (int t = 0; t < 2; ++t)
        #pragma unroll
        for (int j = 0; j < 8; ++j)
            #pragma unroll
            for (int e = 0; e < 4; ++e) acc[t][j][e] = 0.f;

    const int KT = K >> 4;

    // ---- load stage 0 directly to smem ----
    {
        #pragma unroll
        for (int i = 0; i < 2; ++i) {
            int f4 = tid + i * 256;
            int row = f4 >> 2, c4 = f4 & 3;
            float4 v = *(const float4*)&A[(size_t)(mBase + row) * K + c4 * 4];
            uint32_t* dst = &As[0][row * AS_STRIDE + c4 * 4];
            dst[0] = f2tf32(v.x); dst[1] = f2tf32(v.y);
            dst[2] = f2tf32(v.z); dst[3] = f2tf32(v.w);
        }
        #pragma unroll
        for (int i = 0; i < 2; ++i) {
            int f4 = tid + i * 256;
            int row = f4 >> 5, c4 = f4 & 31;
            const float* src = &B[(size_t)row * N + nBase + c4 * 4];
            float4 v;
            if (fullN) v = *(const float4*)src;
            else {
                int n0 = nBase + c4 * 4;
                v.x = (n0 + 0 < N) ? src[0] : 0.f;
                v.y = (n0 + 1 < N) ? src[1] : 0.f;
                v.z = (n0 + 2 < N) ? src[2] : 0.f;
                v.w = (n0 + 3 < N) ? src[3] : 0.f;
            }
            uint32_t* dst = &Bs[0][row * BS_STRIDE + c4 * 4];
            dst[0] = f2tf32(v.x); dst[1] = f2tf32(v.y);
            dst[2] = f2tf32(v.z); dst[3] = f2tf32(v.w);
        }
    }
    __syncthreads();

    for (int kt = 0; kt < KT; ++kt) {
        const int buf = kt & 1;
        const int k0n = (kt + 1) << 4;

        // prefetch next stage into registers
        float4 pa[2], pb[2];
        if (kt + 1 < KT) {
            #pragma unroll
            for (int i = 0; i < 2; ++i) {
                int f4 = tid + i * 256;
                int row = f4 >> 2, c4 = f4 & 3;
                pa[i] = *(const float4*)&A[(size_t)(mBase + row) * K + k0n + c4 * 4];
            }
            #pragma unroll
            for (int i = 0; i < 2; ++i) {
                int f4 = tid + i * 256;
                int row = f4 >> 5, c4 = f4 & 31;
                const float* src = &B[(size_t)(k0n + row) * N + nBase + c4 * 4];
                if (fullN) pb[i] = *(const float4*)src;
                else {
                    int n0 = nBase + c4 * 4;
                    pb[i].x = (n0 + 0 < N) ? src[0] : 0.f;
                    pb[i].y = (n0 + 1 < N) ? src[1] : 0.f;
                    pb[i].z = (n0 + 2 < N) ? src[2] : 0.f;
                    pb[i].w = (n0 + 3 < N) ? src[3] : 0.f;
                }
            }
        }

        // compute on smem[buf]
        #pragma unroll
        for (int ks = 0; ks < 2; ++ks) {
            uint32_t af[2][4];
            #pragma unroll
            for (int t = 0; t < 2; ++t) {
                int rb = wm * 32 + t * 16;
                int kc = ks * 8 + tig;
                af[t][0] = As[buf][(rb + gid)     * AS_STRIDE + kc];
                af[t][1] = As[buf][(rb + gid + 8) * AS_STRIDE + kc];
                af[t][2] = As[buf][(rb + gid)     * AS_STRIDE + kc + 4];
                af[t][3] = As[buf][(rb + gid + 8) * AS_STRIDE + kc + 4];
            }
            uint32_t bf[8][2];
            #pragma unroll
            for (int j = 0; j < 8; ++j) {
                int col = wn * 64 + j * 8 + gid;
                bf[j][0] = Bs[buf][(ks * 8 + tig)     * BS_STRIDE + col];
                bf[j][1] = Bs[buf][(ks * 8 + tig + 4) * BS_STRIDE + col];
            }
            #pragma unroll
            for (int t = 0; t < 2; ++t)
                #pragma unroll
                for (int j = 0; j < 8; ++j) {
                    asm volatile(
                        "mma.sync.aligned.m16n8k8.row.col.f32.tf32.tf32.f32 "
                        "{%0,%1,%2,%3}, {%4,%5,%6,%7}, {%8,%9}, {%0,%1,%2,%3};\n"
                        : "+f"(acc[t][j][0]), "+f"(acc[t][j][1]),
                          "+f"(acc[t][j][2]), "+f"(acc[t][j][3])
                        : "r"(af[t][0]), "r"(af[t][1]), "r"(af[t][2]), "r"(af[t][3]),
                          "r"(bf[j][0]), "r"(bf[j][1]));
                }
        }

        // store prefetched stage
        if (kt + 1 < KT) {
            #pragma unroll
            for (int i = 0; i < 2; ++i) {
                int f4 = tid + i * 256;
                int row = f4 >> 2, c4 = f4 & 3;
                uint32_t* dst = &As[buf ^ 1][row * AS_STRIDE + c4 * 4];
                dst[0] = f2tf32(pa[i].x); dst[1] = f2tf32(pa[i].y);
                dst[2] = f2tf32(pa[i].z); dst[3] = f2tf32(pa[i].w);
            }
            #pragma unroll
            for (int i = 0; i < 2; ++i) {
                int f4 = tid + i * 256;
                int row = f4 >> 5, c4 = f4 & 31;
                uint32_t* dst = &Bs[buf ^ 1][row * BS_STRIDE + c4 * 4];
                dst[0] = f2tf32(pb[i].x); dst[1] = f2tf32(pb[i].y);
                dst[2] = f2tf32(pb[i].z); dst[3] = f2tf32(pb[i].w);
            }
            __syncthreads();
        }
    }

    // epilogue
    #pragma unroll
    for (int t = 0; t < 2; ++t) {
        int r0 = mBase + wm * 32 + t * 16 + gid;
        #pragma unroll
        for (int j = 0; j < 8; ++j) {
            int c0 = nBase + wn * 64 + j * 8 + tig * 2;
            if (c0 + 1 < N) {
                *(float2*)&C[(size_t)r0 * N + c0]       = make_float2(acc[t][j][0], acc[t][j][1]);
                *(float2*)&C[(size_t)(r0 + 8) * N + c0] = make_float2(acc[t][j][2], acc[t][j][3]);
            } else if (c0 < N) {
                C[(size_t)r0 * N + c0]       = acc[t][j][0];
                C[(size_t)(r0 + 8) * N + c0] = acc[t][j][2];
            }
        }
    }
}

// ---------------- causal depthwise conv (k=4) + SiLU ----------------
__global__ __launch_bounds__(256) void conv_silu_kernel(
    const float* __restrict__ conv_w, const float* __restrict__ conv_b)
{
    int idx = blockIdx.x * 256 + threadIdx.x;
    if (idx >= ROWS * CONVD) return;
    int r = idx / CONVD;
    int c = idx - r * CONVD;
    int l = r & (LSEQ - 1);

    float acc = conv_b[c];
    #pragma unroll
    for (int i = 0; i < 4; ++i) {
        int ll = l - 3 + i;
        if (ll >= 0)
            acc = fmaf(g_zxbcdt[(size_t)(r - 3 + i) * DPROJ + DIEXP + c],
                       conv_w[c * 4 + i], acc);
    }
    float s = acc / (1.f + expf(-acc));
    g_xconv[(size_t)r * CONVD + c] = s;
}

// ---------------- dt = softplus(raw + bias), adt = A * dt ----------------
__global__ __launch_bounds__(256) void dt_kernel(
    const float* __restrict__ dt_bias, const float* __restrict__ A_log)
{
    int idx = blockIdx.x * 256 + threadIdx.x;
    if (idx >= ROWS * NH) return;
    int r = idx >> 5;
    int h = idx & 31;
    float x = g_zxbcdt[(size_t)r * DPROJ + (DPROJ - NH) + h] + dt_bias[h];
    float sp = (x > 20.f) ? x : log1pf(expf(x));
    g_dt[idx]  = sp;
    g_adt[idx] = -expf(A_log[h]) * sp;
}

// ---------------- CB[b,c,i,j] = sum_n C[i,n] * B[j,n] ----------------
__global__ __launch_bounds__(256) void cb_kernel()
{
    __shared__ float Cs[64][65];
    __shared__ float Bs[64][65];
    const int bc = blockIdx.x;
    const int rowBase = bc * CS;
    const int tid = threadIdx.x;
    const int tx = tid & 15, ty = tid >> 4;

    float acc[4][4];
    #pragma unroll
    for (int a = 0; a < 4; ++a)
        #pragma unroll
        for (int b2 = 0; b2 < 4; ++b2) acc[a][b2] = 0.f;

    for (int n0 = 0; n0 < DS; n0 += 64) {
        for (int t = tid; t < 4096; t += 256) {
            int i = t >> 6, n = t & 63;
            const size_t row = (size_t)(rowBase + i) * CONVD;
            Cs[i][n] = g_xconv[row + DIEXP + DS + n0 + n];
            Bs[i][n] = g_xconv[row + DIEXP + n0 + n];
        }
        __syncthreads();
        for (int n = 0; n < 64; ++n) {
            float cr[4], br[4];
            #pragma unroll
            for (int a = 0; a < 4; ++a)  cr[a]  = Cs[ty * 4 + a][n];
            #pragma unroll
            for (int b2 = 0; b2 < 4; ++b2) br[b2] = Bs[tx * 4 + b2][n];
            #pragma unroll
            for (int a = 0; a < 4; ++a)
                #pragma unroll
                for (int b2 = 0; b2 < 4; ++b2)
                    acc[a][b2] = fmaf(cr[a], br[b2], acc[a][b2]);
        }
        __syncthreads();
    }
    #pragma unroll
    for (int a = 0; a < 4; ++a)
        #pragma unroll
        for (int b2 = 0; b2 < 4; ++b2)
            g_CB[bc * 4096 + (ty * 4 + a) * 64 + tx * 4 + b2] = acc[a][b2];
}

// ---------------- per-chunk states ----------------
__global__ __launch_bounds__(256) void states_kernel()
{
    const int c = blockIdx.x, b = blockIdx.y, h = blockIdx.z;
    const int tid = threadIdx.x;
    const int tx = tid & 15, ty = tid >> 4;
    const int rowBase = b * LSEQ + c * CS;

    __shared__ float a_s[CS];
    __shared__ float acum[CS];
    __shared__ float xw[CS][64];
    __shared__ float Bs[CS][64];

    if (tid < CS) a_s[tid] = g_adt[(rowBase + tid) * NH + h];
    __syncthreads();
    if (tid == 0) {
        float s = 0.f;
        #pragma unroll
        for (int i = 0; i < CS; ++i) { s += a_s[i]; acum[i] = s; }
        g_dchunk[(b * NC + c) * NH + h] = expf(s);
    }
    __syncthreads();

    const float aend = acum[CS - 1];
    for (int t = tid; t < CS * 64; t += 256) {
        int s = t >> 6, p = t & 63;
        float w = expf(aend - acum[s]);
        xw[s][p] = g_xconv[(size_t)(rowBase + s) * CONVD + h * HP + p]
                   * g_dt[(rowBase + s) * NH + h] * w;
    }

    const size_t obase = ((size_t)((b * NC + c) * NH + h)) * (HP * DS);
    for (int n0 = 0; n0 < DS; n0 += 64) {
        for (int t = tid; t < CS * 64; t += 256) {
            int s = t >> 6, n = t & 63;
            Bs[s][n] = g_xconv[(size_t)(rowBase + s) * CONVD + DIEXP + n0 + n];
        }
        __syncthreads();
        float acc[4][4];
        #pragma unroll
        for (int a = 0; a < 4; ++a)
            #pragma unroll
            for (int b2 = 0; b2 < 4; ++b2) acc[a][b2] = 0.f;
        for (int s = 0; s < CS; ++s) {
            float xr[4], br[4];
            #pragma unroll
            for (int a = 0; a < 4; ++a)  xr[a]  = xw[s][ty * 4 + a];
            #pragma unroll
            for (int b2 = 0; b2 < 4; ++b2) br[b2] = Bs[s][tx * 4 + b2];
            #pragma unroll
            for (int a = 0; a < 4; ++a)
                #pragma unroll
                for (int b2 = 0; b2 < 4; ++b2)
                    acc[a][b2] = fmaf(xr[a], br[b2], acc[a][b2]);
        }
        #pragma unroll
        for (int a = 0; a < 4; ++a)
            #pragma unroll
            for (int b2 = 0; b2 < 4; ++b2)
                g_states[obase + (size_t)(ty * 4 + a) * DS + n0 + tx * 4 + b2] = acc[a][b2];
        __syncthreads();
    }
}

// ---------------- inter-chunk recurrence, one thread per element ------------
// states_in[c] written; S <- states[c] + exp(dA[c]) * S
__global__ __launch_bounds__(256) void recur_kernel()
{
    const int bid = blockIdx.x;        // 0 .. BSZ*NH*32-1
    const int bh  = bid >> 5;          // (b*NH + h)
    const int eo  = ((bid & 31) << 8) + threadIdx.x;   // 0..8191
    const int b = bh >> 5, h = bh & 31;

    float S = 0.f;
    for (int c = 0; c < NC; ++c) {
        float d = g_dchunk[(b * NC + c) * NH + h];
        size_t idx = ((size_t)((b * NC + c) * NH + h)) * (HP * DS) + eo;
        float t = g_states[idx];
        g_states[idx] = S;
        S = fmaf(d, S, t);
    }
}

// ---------------- Y = Y_off + Y_diag per (b,c,h) -----------------------------
__global__ __launch_bounds__(256) void y_kernel()
{
    const int c = blockIdx.x, b = blockIdx.y, h = blockIdx.z;
    const int tid = threadIdx.x;
    const int tx = tid & 15, ty = tid >> 4;
    const int rowBase = b * LSEQ + c * CS;

    __shared__ float a_s[CS];
    __shared__ float acum[CS];
    __shared__ float sA[CS][65];
    __shared__ float sB[CS][65];

    if (tid < CS) a_s[tid] = g_adt[(rowBase + tid) * NH + h];
    __syncthreads();
    if (tid == 0) {
        float s = 0.f;
        #pragma unroll
        for (int i = 0; i < CS; ++i) { s += a_s[i]; acum[i] = s; }
    }
    __syncthreads();

    float acc[4][4];
    #pragma unroll
    for (int a = 0; a < 4; ++a)
        #pragma unroll
        for (int b2 = 0; b2 < 4; ++b2) acc[a][b2] = 0.f;

    const size_t sbase = ((size_t)((b * NC + c) * NH + h)) * (HP * DS);
    for (int n0 = 0; n0 < DS; n0 += 64) {
        for (int t = tid; t < 4096; t += 256) {
            int i = t >> 6, n = t & 63;
            sA[i][n] = g_xconv[(size_t)(rowBase + i) * CONVD + DIEXP + DS + n0 + n];
            sB[i][n] = g_states[sbase + (size_t)i * DS + n0 + n];
        }
        __syncthreads();
        for (int n = 0; n < 64; ++n) {
            float cr[4], sr[4];
            #pragma unroll
            for (int a = 0; a < 4; ++a)  cr[a]  = sA[ty * 4 + a][n];
            #pragma unroll
            for (int b2 = 0; b2 < 4; ++b2) sr[b2] = sB[tx * 4 + b2][n];
            #pragma unroll
            for (int a = 0; a < 4; ++a)
                #pragma unroll
                for (int b2 = 0; b2 < 4; ++b2)
                    acc[a][b2] = fmaf(cr[a], sr[b2], acc[a][b2]);
        }
        __syncthreads();
    }
    #pragma unroll
    for (int a = 0; a < 4; ++a) {
        float ei = expf(acum[ty * 4 + a]);
        #pragma unroll
        for (int b2 = 0; b2 < 4; ++b2) acc[a][b2] *= ei;
    }

    const int cbBase = (b * NC + c) * 4096;
    for (int t = tid; t < 4096; t += 256) {
        int i = t >> 6, jj = t & 63;
        float w = 0.f;
        if (jj <= i) w = g_CB[cbBase + i * 64 + jj] * expf(acum[i] - acum[jj]);
        sA[i][jj] = w;
        sB[i][jj] = g_xconv[(size_t)(rowBase + i) * CONVD + h * HP + jj]
                    * g_dt[(rowBase + i) * NH + h];
    }
    __syncthreads();
    for (int j = 0; j < 64; ++j) {
        float wr[4], xr[4];
        #pragma unroll
        for (int a = 0; a < 4; ++a)  wr[a]  = sA[ty * 4 + a][j];
        #pragma unroll
        for (int b2 = 0; b2 < 4; ++b2) xr[b2] = sB[j][tx * 4 + b2];
        #pragma unroll
        for (int a = 0; a < 4; ++a)
            #pragma unroll
            for (int b2 = 0; b2 < 4; ++b2)
                acc[a][b2] = fmaf(wr[a], xr[b2], acc[a][b2]);
    }

    #pragma unroll
    for (int a = 0; a < 4; ++a)
        #pragma unroll
        for (int b2 = 0; b2 < 4; ++b2)
            g_y[(size_t)(rowBase + ty * 4 + a) * DIEXP + h * HP + tx * 4 + b2]
                = acc[a][b2];
}

// ---------------- gate (y * silu(z)) + LayerNorm -----------------------------
__global__ __launch_bounds__(256) void gatenorm_kernel(
    const float* __restrict__ norm_w, const float* __restrict__ norm_b)
{
    const int r = blockIdx.x;
    const int tid = threadIdx.x;
    __shared__ float red[256];

    float v[8];
    float lsum = 0.f;
    #pragma unroll
    for (int e = 0; e < 8; ++e) {
        int col = e * 256 + tid;
        float z  = g_zxbcdt[(size_t)r * DPROJ + col];
        float yv = g_y[(size_t)r * DIEXP + col];
        float val = yv * (z / (1.f + expf(-z)));
        v[e] = val;
        lsum += val;
    }
    red[tid] = lsum;
    __syncthreads();
    for (int o = 128; o > 0; o >>= 1) {
        if (tid < o) red[tid] += red[tid + o];
        __syncthreads();
    }
    float mu = red[0] / (float)DIEXP;
    __syncthreads();

    float ls2 = 0.f;
    #pragma unroll
    for (int e = 0; e < 8; ++e) { float d = v[e] - mu; ls2 = fmaf(d, d, ls2); }
    red[tid] = ls2;
    __syncthreads();
    for (int o = 128; o > 0; o >>= 1) {
        if (tid < o) red[tid] += red[tid + o];
        __syncthreads();
    }
    float rstd = rsqrtf(red[0] / (float)DIEXP + 1e-5f);

    #pragma unroll
    for (int e = 0; e < 8; ++e) {
        int col = e * 256 + tid;
        g_y[(size_t)r * DIEXP + col] = (v[e] - mu) * rstd * norm_w[col] + norm_b[col];
    }
}

// ---------------- launch -----------------------------------------------------
extern "C" void kernel_launch(void* const* d_in, const int* in_sizes, int n_in,
                              void* d_out, int out_size)
{
    const float* u       = (const float*)d_in[0];
    const float* W_in    = (const float*)d_in[1];
    const float* conv_w  = (const float*)d_in[2];
    const float* conv_b  = (const float*)d_in[3];
    const float* dt_bias = (const float*)d_in[4];
    const float* A_log   = (const float*)d_in[5];
    const float* norm_w  = (const float*)d_in[6];
    const float* norm_b  = (const float*)d_in[7];
    const float* W_out   = (const float*)d_in[8];
    float* out = (float*)d_out;

    float *zx = nullptr, *yb = nullptr;
    cudaGetSymbolAddress((void**)&zx, g_zxbcdt);
    cudaGetSymbolAddress((void**)&yb, g_y);

    // 1) zxbcdt = u @ W_in    (8192 x 4384, K=1024)  — tf32 tensor cores
    gemm_tf32_kernel<<<dim3((DPROJ + 127) / 128, ROWS / 128), 256>>>(
        u, W_in, zx, ROWS, DPROJ, DMODEL);
    // 2) causal dwconv + silu
    conv_silu_kernel<<<(ROWS * CONVD + 255) / 256, 256>>>(conv_w, conv_b);
    // 3) dt / A*dt
    dt_kernel<<<(ROWS * NH + 255) / 256, 256>>>(dt_bias, A_log);
    // 4) CB gram matrices per (b, chunk)
    cb_kernel<<<BSZ * NC, 256>>>();
    // 5) per-chunk states
    states_kernel<<<dim3(NC, BSZ, NH), 256>>>();
    // 6) inter-chunk recurrence (fully parallel over elements)
    recur_kernel<<<BSZ * NH * 32, 256>>>();
    // 7) Y = Yd + Yoff
    y_kernel<<<dim3(NC, BSZ, NH), 256>>>();
    // 8) gate + layernorm
    gatenorm_kernel<<<ROWS, 256>>>(norm_w, norm_b);
    // 9) out = y @ W_out      (8192 x 1024, K=2048)  — tf32 tensor cores
    gemm_tf32_kernel<<<dim3(DMODEL / 128, ROWS / 128), 256>>>(
        yb, W_out, out, ROWS, DMODEL, DIEXP);
}

// round 6
// speedup vs baseline: 2.4643x; 1.0713x over previous
#include <cuda_runtime.h>
#include <math.h>
#include <stdint.h>

// ---------------- problem constants ----------------
#define BSZ    2
#define LSEQ   4096
#define DMODEL 1024
#define DIEXP  2048
#define NH     32
#define HP     64
#define DS     128
#define CS     64
#define NC     64
#define DPROJ  4384
#define CONVD  2304
#define ROWS   8192

// ---------------- device scratch ----------------
__device__ float g_zxbcdt[(size_t)ROWS * DPROJ];
__device__ float g_xconv [(size_t)ROWS * CONVD];
__device__ float g_dt    [ROWS * NH];
__device__ float g_adt   [ROWS * NH];
__device__ float g_CB    [BSZ * NC * CS * CS];
__device__ float g_states[(size_t)BSZ * NC * NH * HP * DS];  // head reused as rounded-u scratch
__device__ float g_dchunk[BSZ * NC * NH];
__device__ float g_y     [(size_t)ROWS * DIEXP];
__device__ float g_WT    [(size_t)DPROJ * DMODEL + (size_t)DMODEL * DIEXP]; // W_in^T, W_out^T (tf32, K-major)

// ---------------- helpers ----------------
__device__ __forceinline__ uint32_t f2tf32(float x) {
    uint32_t r;
    asm("cvt.rna.tf32.f32 %0, %1;" : "=r"(r) : "f"(x));
    return r;
}
__device__ __forceinline__ float tf32r(float x) { return __uint_as_float(f2tf32(x)); }

__device__ __forceinline__ uint32_t smem_u32(const void* p) {
    uint32_t a;
    asm("{ .reg .u64 t; cvta.to.shared.u64 t, %1; cvt.u32.u64 %0, t; }" : "=r"(a) : "l"(p));
    return a;
}
__device__ __forceinline__ void cp_async16(uint32_t dst, const void* src) {
    asm volatile("cp.async.cg.shared.global [%0], [%1], 16;" :: "r"(dst), "l"(src) : "memory");
}
#define SWZ(o) ((o) ^ (((o) >> 3) & 0x70))

// =====================================================================
// tf32 mma.sync GEMM: C = A(MxK) @ BT(NxK)^T, fp32 (tf32-valued) inputs.
// Block 128x128, BK=32, 256 threads (8 warps 4x2, warp tile 32x64).
// 3-stage cp.async ring, SW128-swizzled smem, one sync per K-tile.
// M%128==0, K%32==0; N edge clamped on load / guarded on store.
// =====================================================================
#define GSTG 3
#define STG_BYTES 16384

__global__ __launch_bounds__(256) void gemm_mma_kernel(
    const float* __restrict__ A, const float* __restrict__ BT,
    float* __restrict__ C, int M, int N, int K)
{
    extern __shared__ char sm[];
    const uint32_t sb = smem_u32(sm);
    const int tid  = threadIdx.x;
    const int wid  = tid >> 5, lane = tid & 31;
    const int gid  = lane >> 2, tig = lane & 3;
    const int wm   = wid >> 1,  wn  = wid & 1;
    const int mBase = blockIdx.y * 128, nBase = blockIdx.x * 128;

    float acc[2][8][4];
    #pragma unroll
    for (int t = 0; t < 2; ++t)
        #pragma unroll
        for (int j = 0; j < 8; ++j)
            #pragma unroll
            for (int e = 0; e < 4; ++e) acc[t][j][e] = 0.f;

    const int KT = K >> 5;
    const int lrow = tid >> 3, lc16 = tid & 7;          // load mapping helpers

    // issue loads for K-tile kt into stage s
    auto load_stage = [&](int kt, int s) {
        const int k0 = kt << 5;
        const uint32_t ab = sb + s * STG_BYTES;
        const uint32_t bb = sb + GSTG * STG_BYTES + s * STG_BYTES;
        #pragma unroll
        for (int i = 0; i < 4; ++i) {
            int row = lrow + i * 32;
            cp_async16(ab + SWZ(row * 128 + lc16 * 16),
                       A + (size_t)(mBase + row) * K + k0 + lc16 * 4);
        }
        #pragma unroll
        for (int i = 0; i < 4; ++i) {
            int row = lrow + i * 32;
            int nr = nBase + row; if (nr >= N) nr = N - 1;
            cp_async16(bb + SWZ(row * 128 + lc16 * 16),
                       BT + (size_t)nr * K + k0 + lc16 * 4);
        }
        asm volatile("cp.async.commit_group;" ::: "memory");
    };

    load_stage(0, 0);
    if (KT > 1) load_stage(1, 1);

    for (int kt = 0; kt < KT; ++kt) {
        const int s = kt % GSTG;
        asm volatile("cp.async.wait_group 1;" ::: "memory");
        __syncthreads();

        const char* As = sm + s * STG_BYTES;
        const char* Bs = sm + GSTG * STG_BYTES + s * STG_BYTES;

        #pragma unroll
        for (int ks = 0; ks < 4; ++ks) {
            const int k = ks * 8;
            uint32_t af[2][4];
            #pragma unroll
            for (int t = 0; t < 2; ++t) {
                int r0 = wm * 32 + t * 16 + gid;
                af[t][0] = *(const uint32_t*)(As + SWZ(r0 * 128 + (k + tig) * 4));
                af[t][1] = *(const uint32_t*)(As + SWZ((r0 + 8) * 128 + (k + tig) * 4));
                af[t][2] = *(const uint32_t*)(As + SWZ(r0 * 128 + (k + tig + 4) * 4));
                af[t][3] = *(const uint32_t*)(As + SWZ((r0 + 8) * 128 + (k + tig + 4) * 4));
            }
            uint32_t bf[8][2];
            #pragma unroll
            for (int j = 0; j < 8; ++j) {
                int col = wn * 64 + j * 8 + gid;
                bf[j][0] = *(const uint32_t*)(Bs + SWZ(col * 128 + (k + tig) * 4));
                bf[j][1] = *(const uint32_t*)(Bs + SWZ(col * 128 + (k + tig + 4) * 4));
            }
            #pragma unroll
            for (int t = 0; t < 2; ++t)
                #pragma unroll
                for (int j = 0; j < 8; ++j) {
                    asm volatile(
                        "mma.sync.aligned.m16n8k8.row.col.f32.tf32.tf32.f32 "
                        "{%0,%1,%2,%3}, {%4,%5,%6,%7}, {%8,%9}, {%0,%1,%2,%3};\n"
                        : "+f"(acc[t][j][0]), "+f"(acc[t][j][1]),
                          "+f"(acc[t][j][2]), "+f"(acc[t][j][3])
                        : "r"(af[t][0]), "r"(af[t][1]), "r"(af[t][2]), "r"(af[t][3]),
                          "r"(bf[j][0]), "r"(bf[j][1]));
                }
        }

        if (kt + 2 < KT) load_stage(kt + 2, (kt + 2) % GSTG);
    }

    // epilogue
    #pragma unroll
    for (int t = 0; t < 2; ++t) {
        int r0 = mBase + wm * 32 + t * 16 + gid;
        #pragma unroll
        for (int j = 0; j < 8; ++j) {
            int c0 = nBase + wn * 64 + j * 8 + tig * 2;
            if (c0 + 1 < N) {
                *(float2*)&C[(size_t)r0 * N + c0]       = make_float2(acc[t][j][0], acc[t][j][1]);
                *(float2*)&C[(size_t)(r0 + 8) * N + c0] = make_float2(acc[t][j][2], acc[t][j][3]);
            } else if (c0 < N) {
                C[(size_t)r0 * N + c0]       = acc[t][j][0];
                C[(size_t)(r0 + 8) * N + c0] = acc[t][j][2];
            }
        }
    }
}

// ---------------- pre-rounding / weight transpose ----------------
__global__ __launch_bounds__(256) void round_u_kernel(const float* __restrict__ u, float* __restrict__ o)
{
    int idx = blockIdx.x * 256 + threadIdx.x;
    if (idx < ROWS * DMODEL / 4) {
        float4 v = ((const float4*)u)[idx];
        v.x = tf32r(v.x); v.y = tf32r(v.y); v.z = tf32r(v.z); v.w = tf32r(v.w);
        ((float4*)o)[idx] = v;
    }
}

// WT[n][k] = round(W[k][n]);  W: K x N row-major
__global__ __launch_bounds__(256) void transpose_round_kernel(
    const float* __restrict__ W, float* __restrict__ WT, int K, int N)
{
    __shared__ float tile[32][33];
    const int bx = blockIdx.x * 32, by = blockIdx.y * 32;
    const int x = threadIdx.x & 31, y = threadIdx.x >> 5;
    #pragma unroll
    for (int i = 0; i < 32; i += 8) {
        int k = by + y + i, n = bx + x;
        tile[y + i][x] = (k < K && n < N) ? W[(size_t)k * N + n] : 0.f;
    }
    __syncthreads();
    #pragma unroll
    for (int i = 0; i < 32; i += 8) {
        int n = bx + y + i, k = by + x;
        if (n < N && k < K) WT[(size_t)n * K + k] = tf32r(tile[x][y + i]);
    }
}

// ---------------- causal depthwise conv (k=4) + SiLU ----------------
__global__ __launch_bounds__(256) void conv_silu_kernel(
    const float* __restrict__ conv_w, const float* __restrict__ conv_b)
{
    int idx = blockIdx.x * 256 + threadIdx.x;
    if (idx >= ROWS * CONVD) return;
    int r = idx / CONVD;
    int c = idx - r * CONVD;
    int l = r & (LSEQ - 1);

    float acc = conv_b[c];
    #pragma unroll
    for (int i = 0; i < 4; ++i) {
        int ll = l - 3 + i;
        if (ll >= 0)
            acc = fmaf(g_zxbcdt[(size_t)(r - 3 + i) * DPROJ + DIEXP + c],
                       conv_w[c * 4 + i], acc);
    }
    float s = acc / (1.f + expf(-acc));
    g_xconv[(size_t)r * CONVD + c] = s;
}

// ---------------- dt / A*dt ----------------
__global__ __launch_bounds__(256) void dt_kernel(
    const float* __restrict__ dt_bias, const float* __restrict__ A_log)
{
    int idx = blockIdx.x * 256 + threadIdx.x;
    if (idx >= ROWS * NH) return;
    int r = idx >> 5;
    int h = idx & 31;
    float x = g_zxbcdt[(size_t)r * DPROJ + (DPROJ - NH) + h] + dt_bias[h];
    float sp = (x > 20.f) ? x : log1pf(expf(x));
    g_dt[idx]  = sp;
    g_adt[idx] = -expf(A_log[h]) * sp;
}

// ---------------- CB gram ----------------
__global__ __launch_bounds__(256) void cb_kernel()
{
    __shared__ float Cs[64][65];
    __shared__ float Bs[64][65];
    const int bc = blockIdx.x;
    const int rowBase = bc * CS;
    const int tid = threadIdx.x;
    const int tx = tid & 15, ty = tid >> 4;

    float acc[4][4];
    #pragma unroll
    for (int a = 0; a < 4; ++a)
        #pragma unroll
        for (int b2 = 0; b2 < 4; ++b2) acc[a][b2] = 0.f;

    for (int n0 = 0; n0 < DS; n0 += 64) {
        for (int t = tid; t < 4096; t += 256) {
            int i = t >> 6, n = t & 63;
            const size_t row = (size_t)(rowBase + i) * CONVD;
            Cs[i][n] = g_xconv[row + DIEXP + DS + n0 + n];
            Bs[i][n] = g_xconv[row + DIEXP + n0 + n];
        }
        __syncthreads();
        for (int n = 0; n < 64; ++n) {
            float cr[4], br[4];
            #pragma unroll
            for (int a = 0; a < 4; ++a)  cr[a]  = Cs[ty * 4 + a][n];
            #pragma unroll
            for (int b2 = 0; b2 < 4; ++b2) br[b2] = Bs[tx * 4 + b2][n];
            #pragma unroll
            for (int a = 0; a < 4; ++a)
                #pragma unroll
                for (int b2 = 0; b2 < 4; ++b2)
                    acc[a][b2] = fmaf(cr[a], br[b2], acc[a][b2]);
        }
        __syncthreads();
    }
    #pragma unroll
    for (int a = 0; a < 4; ++a)
        #pragma unroll
        for (int b2 = 0; b2 < 4; ++b2)
            g_CB[bc * 4096 + (ty * 4 + a) * 64 + tx * 4 + b2] = acc[a][b2];
}

// ---------------- per-chunk states ----------------
__global__ __launch_bounds__(256) void states_kernel()
{
    const int c = blockIdx.x, b = blockIdx.y, h = blockIdx.z;
    const int tid = threadIdx.x;
    const int tx = tid & 15, ty = tid >> 4;
    const int rowBase = b * LSEQ + c * CS;

    __shared__ float a_s[CS];
    __shared__ float acum[CS];
    __shared__ float xw[CS][64];
    __shared__ float Bs[CS][64];

    if (tid < CS) a_s[tid] = g_adt[(rowBase + tid) * NH + h];
    __syncthreads();
    if (tid == 0) {
        float s = 0.f;
        #pragma unroll
        for (int i = 0; i < CS; ++i) { s += a_s[i]; acum[i] = s; }
        g_dchunk[(b * NC + c) * NH + h] = expf(s);
    }
    __syncthreads();

    const float aend = acum[CS - 1];
    for (int t = tid; t < CS * 64; t += 256) {
        int s = t >> 6, p = t & 63;
        float w = expf(aend - acum[s]);
        xw[s][p] = g_xconv[(size_t)(rowBase + s) * CONVD + h * HP + p]
                   * g_dt[(rowBase + s) * NH + h] * w;
    }

    const size_t obase = ((size_t)((b * NC + c) * NH + h)) * (HP * DS);
    for (int n0 = 0; n0 < DS; n0 += 64) {
        for (int t = tid; t < CS * 64; t += 256) {
            int s = t >> 6, n = t & 63;
            Bs[s][n] = g_xconv[(size_t)(rowBase + s) * CONVD + DIEXP + n0 + n];
        }
        __syncthreads();
        float acc[4][4];
        #pragma unroll
        for (int a = 0; a < 4; ++a)
            #pragma unroll
            for (int b2 = 0; b2 < 4; ++b2) acc[a][b2] = 0.f;
        for (int s = 0; s < CS; ++s) {
            float4 xr = *(const float4*)&xw[s][ty * 4];
            float4 br = *(const float4*)&Bs[s][tx * 4];
            float xa[4] = {xr.x, xr.y, xr.z, xr.w};
            float bb[4] = {br.x, br.y, br.z, br.w};
            #pragma unroll
            for (int a = 0; a < 4; ++a)
                #pragma unroll
                for (int b2 = 0; b2 < 4; ++b2)
                    acc[a][b2] = fmaf(xa[a], bb[b2], acc[a][b2]);
        }
        #pragma unroll
        for (int a = 0; a < 4; ++a)
            #pragma unroll
            for (int b2 = 0; b2 < 4; ++b2)
                g_states[obase + (size_t)(ty * 4 + a) * DS + n0 + tx * 4 + b2] = acc[a][b2];
        __syncthreads();
    }
}

// ---------------- inter-chunk recurrence ----------------
__global__ __launch_bounds__(256) void recur_kernel()
{
    const int bid = blockIdx.x;
    const int bh  = bid >> 5;
    const int eo  = ((bid & 31) << 8) + threadIdx.x;
    const int b = bh >> 5, h = bh & 31;

    float S = 0.f;
    for (int c = 0; c < NC; ++c) {
        float d = g_dchunk[(b * NC + c) * NH + h];
        size_t idx = ((size_t)((b * NC + c) * NH + h)) * (HP * DS) + eo;
        float t = g_states[idx];
        g_states[idx] = S;
        S = fmaf(d, S, t);
    }
}

// ---------------- Y = Y_off + Y_diag (transposed smem, float4 loads) --------
#define YST 68
__global__ __launch_bounds__(256) void y_kernel()
{
    const int c = blockIdx.x, b = blockIdx.y, h = blockIdx.z;
    const int tid = threadIdx.x;
    const int tx = tid & 15, ty = tid >> 4;   // ty -> i (seq), tx -> p
    const int rowBase = b * LSEQ + c * CS;

    __shared__ float a_s[CS];
    __shared__ float acum[CS];
    __shared__ float sT1[CS * YST];   // phase A: C^T[n][i]   phase B: W^T[j][i]
    __shared__ float sT2[CS * YST];   // phase A: Sin^T[n][p] phase B: xdt[j][p]

    if (tid < CS) a_s[tid] = g_adt[(rowBase + tid) * NH + h];
    __syncthreads();
    if (tid == 0) {
        float s = 0.f;
        #pragma unroll
        for (int i = 0; i < CS; ++i) { s += a_s[i]; acum[i] = s; }
    }
    __syncthreads();

    float acc[4][4];
    #pragma unroll
    for (int a = 0; a < 4; ++a)
        #pragma unroll
        for (int b2 = 0; b2 < 4; ++b2) acc[a][b2] = 0.f;

    // ---- Phase A: Yoff[i,p] = exp(acum[i]) * sum_n C[i,n] * Sin[p,n] ----
    const size_t sbase = ((size_t)((b * NC + c) * NH + h)) * (HP * DS);
    for (int n0 = 0; n0 < DS; n0 += 64) {
        for (int t = tid; t < 4096; t += 256) {
            int i = t >> 6, n = t & 63;
            sT1[n * YST + i] = g_xconv[(size_t)(rowBase + i) * CONVD + DIEXP + DS + n0 + n]; // C[i][n]
            sT2[n * YST + i] = g_states[sbase + (size_t)i * DS + n0 + n];                    // Sin[p=i][n]
        }
        __syncthreads();
        for (int n = 0; n < 64; ++n) {
            float4 cr = *(const float4*)&sT1[n * YST + ty * 4];
            float4 sr = *(const float4*)&sT2[n * YST + tx * 4];
            float ca[4] = {cr.x, cr.y, cr.z, cr.w};
            float sa[4] = {sr.x, sr.y, sr.z, sr.w};
            #pragma unroll
            for (int a = 0; a < 4; ++a)
                #pragma unroll
                for (int b2 = 0; b2 < 4; ++b2)
                    acc[a][b2] = fmaf(ca[a], sa[b2], acc[a][b2]);
        }
        __syncthreads();
    }
    #pragma unroll
    for (int a = 0; a < 4; ++a) {
        float ei = expf(acum[ty * 4 + a]);
        #pragma unroll
        for (int b2 = 0; b2 < 4; ++b2) acc[a][b2] *= ei;
    }

    // ---- Phase B: Yd[i,p] = sum_{j<=i} W[i,j] * xdt[j,p] ----
    const int cbBase = (b * NC + c) * 4096;
    for (int t = tid; t < 4096; t += 256) {
        int i = t >> 6, jj = t & 63;
        float w = 0.f;
        if (jj <= i) w = g_CB[cbBase + i * 64 + jj] * expf(acum[i] - acum[jj]);
        sT1[jj * YST + i] = w;                         // W^T[j][i]
        sT2[i * YST + jj] = g_xconv[(size_t)(rowBase + i) * CONVD + h * HP + jj]
                            * g_dt[(rowBase + i) * NH + h];   // xdt[j=i][p=jj]
    }
    __syncthreads();
    for (int j = 0; j < 64; ++j) {
        float4 wr = *(const float4*)&sT1[j * YST + ty * 4];
        float4 xr = *(const float4*)&sT2[j * YST + tx * 4];
        float wa[4] = {wr.x, wr.y, wr.z, wr.w};
        float xa[4] = {xr.x, xr.y, xr.z, xr.w};
        #pragma unroll
        for (int a = 0; a < 4; ++a)
            #pragma unroll
            for (int b2 = 0; b2 < 4; ++b2)
                acc[a][b2] = fmaf(wa[a], xa[b2], acc[a][b2]);
    }

    #pragma unroll
    for (int a = 0; a < 4; ++a)
        #pragma unroll
        for (int b2 = 0; b2 < 4; ++b2)
            g_y[(size_t)(rowBase + ty * 4 + a) * DIEXP + h * HP + tx * 4 + b2]
                = acc[a][b2];
}

// ---------------- gate + LayerNorm (emits tf32-rounded y) ----------------
__global__ __launch_bounds__(256) void gatenorm_kernel(
    const float* __restrict__ norm_w, const float* __restrict__ norm_b)
{
    const int r = blockIdx.x;
    const int tid = threadIdx.x;
    __shared__ float red[256];

    float v[8];
    float lsum = 0.f;
    #pragma unroll
    for (int e = 0; e < 8; ++e) {
        int col = e * 256 + tid;
        float z  = g_zxbcdt[(size_t)r * DPROJ + col];
        float yv = g_y[(size_t)r * DIEXP + col];
        float val = yv * (z / (1.f + expf(-z)));
        v[e] = val;
        lsum += val;
    }
    red[tid] = lsum;
    __syncthreads();
    for (int o = 128; o > 0; o >>= 1) {
        if (tid < o) red[tid] += red[tid + o];
        __syncthreads();
    }
    float mu = red[0] / (float)DIEXP;
    __syncthreads();

    float ls2 = 0.f;
    #pragma unroll
    for (int e = 0; e < 8; ++e) { float d = v[e] - mu; ls2 = fmaf(d, d, ls2); }
    red[tid] = ls2;
    __syncthreads();
    for (int o = 128; o > 0; o >>= 1) {
        if (tid < o) red[tid] += red[tid + o];
        __syncthreads();
    }
    float rstd = rsqrtf(red[0] / (float)DIEXP + 1e-5f);

    #pragma unroll
    for (int e = 0; e < 8; ++e) {
        int col = e * 256 + tid;
        g_y[(size_t)r * DIEXP + col] =
            tf32r((v[e] - mu) * rstd * norm_w[col] + norm_b[col]);
    }
}

// ---------------- launch ----------------
extern "C" void kernel_launch(void* const* d_in, const int* in_sizes, int n_in,
                              void* d_out, int out_size)
{
    const float* u       = (const float*)d_in[0];
    const float* W_in    = (const float*)d_in[1];
    const float* conv_w  = (const float*)d_in[2];
    const float* conv_b  = (const float*)d_in[3];
    const float* dt_bias = (const float*)d_in[4];
    const float* A_log   = (const float*)d_in[5];
    const float* norm_w  = (const float*)d_in[6];
    const float* norm_b  = (const float*)d_in[7];
    const float* W_out   = (const float*)d_in[8];
    float* out = (float*)d_out;

    float *zx = nullptr, *yb = nullptr, *sc = nullptr, *wt = nullptr;
    cudaGetSymbolAddress((void**)&zx, g_zxbcdt);
    cudaGetSymbolAddress((void**)&yb, g_y);
    cudaGetSymbolAddress((void**)&sc, g_states);   // rounded-u scratch (freed before states_kernel)
    cudaGetSymbolAddress((void**)&wt, g_WT);

    const int GEMM_SMEM = 2 * GSTG * STG_BYTES;    // 98304 B
    cudaFuncSetAttribute(gemm_mma_kernel,
                         cudaFuncAttributeMaxDynamicSharedMemorySize, GEMM_SMEM);

    // 0) pre-round u; transpose+round weights to K-major
    round_u_kernel<<<(ROWS * DMODEL / 4 + 255) / 256, 256>>>(u, sc);
    transpose_round_kernel<<<dim3((DPROJ + 31) / 32, (DMODEL + 31) / 32), 256>>>(
        W_in, wt, DMODEL, DPROJ);
    transpose_round_kernel<<<dim3((DMODEL + 31) / 32, (DIEXP + 31) / 32), 256>>>(
        W_out, wt + (size_t)DPROJ * DMODEL, DIEXP, DMODEL);

    // 1) zxbcdt = u @ W_in
    gemm_mma_kernel<<<dim3((DPROJ + 127) / 128, ROWS / 128), 256, GEMM_SMEM>>>(
        sc, wt, zx, ROWS, DPROJ, DMODEL);
    // 2) causal dwconv + silu
    conv_silu_kernel<<<(ROWS * CONVD + 255) / 256, 256>>>(conv_w, conv_b);
    // 3) dt / A*dt
    dt_kernel<<<(ROWS * NH + 255) / 256, 256>>>(dt_bias, A_log);
    // 4) CB gram
    cb_kernel<<<BSZ * NC, 256>>>();
    // 5) per-chunk states (overwrites rounded-u scratch; GEMM1 done)
    states_kernel<<<dim3(NC, BSZ, NH), 256>>>();
    // 6) inter-chunk recurrence
    recur_kernel<<<BSZ * NH * 32, 256>>>();
    // 7) Y
    y_kernel<<<dim3(NC, BSZ, NH), 256>>>();
    // 8) gate + layernorm (emits tf32-rounded y)
    gatenorm_kernel<<<ROWS, 256>>>(norm_w, norm_b);
    // 9) out = y @ W_out
    gemm_mma_kernel<<<dim3(DMODEL / 128, ROWS / 128), 256, GEMM_SMEM>>>(
        yb, wt + (size_t)DPROJ * DMODEL, out, ROWS, DMODEL, DIEXP);
}

// round 7
// speedup vs baseline: 2.5070x; 1.0173x over previous
#include <cuda_runtime.h>
#include <math.h>
#include <stdint.h>

// ---------------- problem constants ----------------
#define BSZ    2
#define LSEQ   4096
#define DMODEL 1024
#define DIEXP  2048
#define NH     32
#define HP     64
#define DS     128
#define CS     64
#define NC     64
#define DPROJ  4384
#define CONVD  2304
#define ROWS   8192

// ---------------- device scratch ----------------
__device__ float g_zxbcdt[(size_t)ROWS * DPROJ];
__device__ float g_xconv [(size_t)ROWS * CONVD];
__device__ float g_dt    [ROWS * NH];
__device__ float g_adt   [ROWS * NH];
__device__ float g_CB    [BSZ * NC * CS * CS];
__device__ float g_states[(size_t)BSZ * NC * NH * HP * DS];  // head reused as rounded-u scratch
__device__ float g_dchunk[BSZ * NC * NH];
__device__ float g_y     [(size_t)ROWS * DIEXP];
__device__ float g_WT    [(size_t)DPROJ * DMODEL + (size_t)DMODEL * DIEXP]; // W_in^T, W_out^T (tf32, K-major)

// ---------------- helpers ----------------
__device__ __forceinline__ uint32_t f2tf32(float x) {
    uint32_t r;
    asm("cvt.rna.tf32.f32 %0, %1;" : "=r"(r) : "f"(x));
    return r;
}
__device__ __forceinline__ float tf32r(float x) { return __uint_as_float(f2tf32(x)); }

__device__ __forceinline__ uint32_t smem_u32(const void* p) {
    uint32_t a;
    asm("{ .reg .u64 t; cvta.to.shared.u64 t, %1; cvt.u32.u64 %0, t; }" : "=r"(a) : "l"(p));
    return a;
}
__device__ __forceinline__ void cp_async16(uint32_t dst, const void* src) {
    asm volatile("cp.async.cg.shared.global [%0], [%1], 16;" :: "r"(dst), "l"(src) : "memory");
}

// =====================================================================
// tf32 mma.sync GEMM: C = A(MxK) @ BT(NxK)^T, fp32 (tf32-valued) inputs.
// Block 128x128, BK=32, 256 threads (8 warps 4x2, warp tile 32x64).
// 3-stage cp.async ring. Padded smem rows (144B = 36 floats): bank
// conflict-free fragment reads with PURE immediate-offset addressing
// (no swizzle ALU in the mainloop).
// M%128==0, K%32==0; N edge clamped on load / guarded on store.
// =====================================================================
#define GSTG 3
#define ROWB 144                 // bytes per smem row (32 floats + 16B pad)
#define STG_BYTES (128 * ROWB)   // 18432

__global__ __launch_bounds__(256) void gemm_mma_kernel(
    const float* __restrict__ A, const float* __restrict__ BT,
    float* __restrict__ C, int M, int N, int K)
{
    extern __shared__ char sm[];
    const uint32_t sb = smem_u32(sm);
    const int tid  = threadIdx.x;
    const int wid  = tid >> 5, lane = tid & 31;
    const int gid  = lane >> 2, tig = lane & 3;
    const int wm   = wid >> 1,  wn  = wid & 1;
    const int mBase = blockIdx.y * 128, nBase = blockIdx.x * 128;

    float acc[2][8][4];
    #pragma unroll
    for (int t = 0; t < 2; ++t)
        #pragma unroll
        for (int j = 0; j < 8; ++j)
            #pragma unroll
            for (int e = 0; e < 4; ++e) acc[t][j][e] = 0.f;

    const int KT = K >> 5;
    const int lrow = tid >> 3, lc16 = tid & 7;

    // per-thread fragment base offsets (bytes, within one stage)
    const int aOff = (wm * 32 + gid) * ROWB + tig * 4;
    const int bOff = (wn * 64 + gid) * ROWB + tig * 4;

    auto load_stage = [&](int kt, int s) {
        const int k0 = kt << 5;
        const uint32_t ab = sb + s * STG_BYTES;
        const uint32_t bb = sb + GSTG * STG_BYTES + s * STG_BYTES;
        #pragma unroll
        for (int i = 0; i < 4; ++i) {
            int row = lrow + i * 32;
            cp_async16(ab + row * ROWB + lc16 * 16,
                       A + (size_t)(mBase + row) * K + k0 + lc16 * 4);
        }
        #pragma unroll
        for (int i = 0; i < 4; ++i) {
            int row = lrow + i * 32;
            int nr = nBase + row; if (nr >= N) nr = N - 1;
            cp_async16(bb + row * ROWB + lc16 * 16,
                       BT + (size_t)nr * K + k0 + lc16 * 4);
        }
        asm volatile("cp.async.commit_group;" ::: "memory");
    };

    load_stage(0, 0);
    if (KT > 1) load_stage(1, 1);

    for (int kt = 0; kt < KT; ++kt) {
        const int s = kt % GSTG;
        asm volatile("cp.async.wait_group 1;" ::: "memory");
        __syncthreads();

        const char* As = sm + s * STG_BYTES + aOff;
        const char* Bs = sm + GSTG * STG_BYTES + s * STG_BYTES + bOff;

        #pragma unroll
        for (int ks = 0; ks < 4; ++ks) {
            const int kb = ks * 32;          // (ks*8)*4 bytes along the row
            uint32_t af[2][4];
            #pragma unroll
            for (int t = 0; t < 2; ++t) {
                const char* a = As + t * (16 * ROWB) + kb;
                af[t][0] = *(const uint32_t*)(a);
                af[t][1] = *(const uint32_t*)(a + 8 * ROWB);
                af[t][2] = *(const uint32_t*)(a + 16);
                af[t][3] = *(const uint32_t*)(a + 8 * ROWB + 16);
            }
            uint32_t bf[8][2];
            #pragma unroll
            for (int j = 0; j < 8; ++j) {
                const char* bp = Bs + j * (8 * ROWB) + kb;
                bf[j][0] = *(const uint32_t*)(bp);
                bf[j][1] = *(const uint32_t*)(bp + 16);
            }
            #pragma unroll
            for (int t = 0; t < 2; ++t)
                #pragma unroll
                for (int j = 0; j < 8; ++j) {
                    asm volatile(
                        "mma.sync.aligned.m16n8k8.row.col.f32.tf32.tf32.f32 "
                        "{%0,%1,%2,%3}, {%4,%5,%6,%7}, {%8,%9}, {%0,%1,%2,%3};\n"
                        : "+f"(acc[t][j][0]), "+f"(acc[t][j][1]),
                          "+f"(acc[t][j][2]), "+f"(acc[t][j][3])
                        : "r"(af[t][0]), "r"(af[t][1]), "r"(af[t][2]), "r"(af[t][3]),
                          "r"(bf[j][0]), "r"(bf[j][1]));
                }
        }

        if (kt + 2 < KT) load_stage(kt + 2, (kt + 2) % GSTG);
    }

    // epilogue
    #pragma unroll
    for (int t = 0; t < 2; ++t) {
        int r0 = mBase + wm * 32 + t * 16 + gid;
        #pragma unroll
        for (int j = 0; j < 8; ++j) {
            int c0 = nBase + wn * 64 + j * 8 + tig * 2;
            if (c0 + 1 < N) {
                *(float2*)&C[(size_t)r0 * N + c0]       = make_float2(acc[t][j][0], acc[t][j][1]);
                *(float2*)&C[(size_t)(r0 + 8) * N + c0] = make_float2(acc[t][j][2], acc[t][j][3]);
            } else if (c0 < N) {
                C[(size_t)r0 * N + c0]       = acc[t][j][0];
                C[(size_t)(r0 + 8) * N + c0] = acc[t][j][2];
            }
        }
    }
}

// ---------------- pre-rounding / weight transpose ----------------
__global__ __launch_bounds__(256) void round_u_kernel(const float* __restrict__ u, float* __restrict__ o)
{
    int idx = blockIdx.x * 256 + threadIdx.x;
    if (idx < ROWS * DMODEL / 4) {
        float4 v = ((const float4*)u)[idx];
        v.x = tf32r(v.x); v.y = tf32r(v.y); v.z = tf32r(v.z); v.w = tf32r(v.w);
        ((float4*)o)[idx] = v;
    }
}

// WT[n][k] = round(W[k][n]);  W: K x N row-major
__global__ __launch_bounds__(256) void transpose_round_kernel(
    const float* __restrict__ W, float* __restrict__ WT, int K, int N)
{
    __shared__ float tile[32][33];
    const int bx = blockIdx.x * 32, by = blockIdx.y * 32;
    const int x = threadIdx.x & 31, y = threadIdx.x >> 5;
    #pragma unroll
    for (int i = 0; i < 32; i += 8) {
        int k = by + y + i, n = bx + x;
        tile[y + i][x] = (k < K && n < N) ? W[(size_t)k * N + n] : 0.f;
    }
    __syncthreads();
    #pragma unroll
    for (int i = 0; i < 32; i += 8) {
        int n = bx + y + i, k = by + x;
        if (n < N && k < K) WT[(size_t)n * K + k] = tf32r(tile[x][y + i]);
    }
}

// ---------------- causal depthwise conv (k=4) + SiLU, float4 ----------------
__global__ __launch_bounds__(256) void conv_silu_kernel(
    const float* __restrict__ conv_w, const float* __restrict__ conv_b)
{
    int idx = blockIdx.x * 256 + threadIdx.x;          // one per 4 channels
    if (idx >= ROWS * (CONVD / 4)) return;
    int r  = idx / (CONVD / 4);
    int c4 = (idx - r * (CONVD / 4)) * 4;
    int l  = r & (LSEQ - 1);

    float4 acc = *(const float4*)&conv_b[c4];
    #pragma unroll
    for (int i = 0; i < 4; ++i) {
        int ll = l - 3 + i;
        if (ll >= 0) {
            float4 x = *(const float4*)&g_zxbcdt[(size_t)(r - 3 + i) * DPROJ + DIEXP + c4];
            acc.x = fmaf(x.x, conv_w[(c4 + 0) * 4 + i], acc.x);
            acc.y = fmaf(x.y, conv_w[(c4 + 1) * 4 + i], acc.y);
            acc.z = fmaf(x.z, conv_w[(c4 + 2) * 4 + i], acc.z);
            acc.w = fmaf(x.w, conv_w[(c4 + 3) * 4 + i], acc.w);
        }
    }
    float4 o;
    o.x = acc.x / (1.f + expf(-acc.x));
    o.y = acc.y / (1.f + expf(-acc.y));
    o.z = acc.z / (1.f + expf(-acc.z));
    o.w = acc.w / (1.f + expf(-acc.w));
    *(float4*)&g_xconv[(size_t)r * CONVD + c4] = o;
}

// ---------------- dt / A*dt ----------------
__global__ __launch_bounds__(256) void dt_kernel(
    const float* __restrict__ dt_bias, const float* __restrict__ A_log)
{
    int idx = blockIdx.x * 256 + threadIdx.x;
    if (idx >= ROWS * NH) return;
    int r = idx >> 5;
    int h = idx & 31;
    float x = g_zxbcdt[(size_t)r * DPROJ + (DPROJ - NH) + h] + dt_bias[h];
    float sp = (x > 20.f) ? x : log1pf(expf(x));
    g_dt[idx]  = sp;
    g_adt[idx] = -expf(A_log[h]) * sp;
}

// ---------------- CB gram ----------------
__global__ __launch_bounds__(256) void cb_kernel()
{
    __shared__ float Cs[64][65];
    __shared__ float Bs[64][65];
    const int bc = blockIdx.x;
    const int rowBase = bc * CS;
    const int tid = threadIdx.x;
    const int tx = tid & 15, ty = tid >> 4;

    float acc[4][4];
    #pragma unroll
    for (int a = 0; a < 4; ++a)
        #pragma unroll
        for (int b2 = 0; b2 < 4; ++b2) acc[a][b2] = 0.f;

    for (int n0 = 0; n0 < DS; n0 += 64) {
        for (int t = tid; t < 4096; t += 256) {
            int i = t >> 6, n = t & 63;
            const size_t row = (size_t)(rowBase + i) * CONVD;
            Cs[i][n] = g_xconv[row + DIEXP + DS + n0 + n];
            Bs[i][n] = g_xconv[row + DIEXP + n0 + n];
        }
        __syncthreads();
        for (int n = 0; n < 64; ++n) {
            float cr[4], br[4];
            #pragma unroll
            for (int a = 0; a < 4; ++a)  cr[a]  = Cs[ty * 4 + a][n];
            #pragma unroll
            for (int b2 = 0; b2 < 4; ++b2) br[b2] = Bs[tx * 4 + b2][n];
            #pragma unroll
            for (int a = 0; a < 4; ++a)
                #pragma unroll
                for (int b2 = 0; b2 < 4; ++b2)
                    acc[a][b2] = fmaf(cr[a], br[b2], acc[a][b2]);
        }
        __syncthreads();
    }
    #pragma unroll
    for (int a = 0; a < 4; ++a)
        #pragma unroll
        for (int b2 = 0; b2 < 4; ++b2)
            g_CB[bc * 4096 + (ty * 4 + a) * 64 + tx * 4 + b2] = acc[a][b2];
}

// ---------------- per-chunk states ----------------
__global__ __launch_bounds__(256) void states_kernel()
{
    const int c = blockIdx.x, b = blockIdx.y, h = blockIdx.z;
    const int tid = threadIdx.x;
    const int tx = tid & 15, ty = tid >> 4;
    const int rowBase = b * LSEQ + c * CS;

    __shared__ float a_s[CS];
    __shared__ float acum[CS];
    __shared__ float xw[CS][64];
    __shared__ float Bs[CS][64];

    if (tid < CS) a_s[tid] = g_adt[(rowBase + tid) * NH + h];
    __syncthreads();
    if (tid == 0) {
        float s = 0.f;
        #pragma unroll
        for (int i = 0; i < CS; ++i) { s += a_s[i]; acum[i] = s; }
        g_dchunk[(b * NC + c) * NH + h] = expf(s);
    }
    __syncthreads();

    const float aend = acum[CS - 1];
    for (int t = tid; t < CS * 64; t += 256) {
        int s = t >> 6, p = t & 63;
        float w = expf(aend - acum[s]);
        xw[s][p] = g_xconv[(size_t)(rowBase + s) * CONVD + h * HP + p]
                   * g_dt[(rowBase + s) * NH + h] * w;
    }

    const size_t obase = ((size_t)((b * NC + c) * NH + h)) * (HP * DS);
    for (int n0 = 0; n0 < DS; n0 += 64) {
        for (int t = tid; t < CS * 64; t += 256) {
            int s = t >> 6, n = t & 63;
            Bs[s][n] = g_xconv[(size_t)(rowBase + s) * CONVD + DIEXP + n0 + n];
        }
        __syncthreads();
        float acc[4][4];
        #pragma unroll
        for (int a = 0; a < 4; ++a)
            #pragma unroll
            for (int b2 = 0; b2 < 4; ++b2) acc[a][b2] = 0.f;
        for (int s = 0; s < CS; ++s) {
            float4 xr = *(const float4*)&xw[s][ty * 4];
            float4 br = *(const float4*)&Bs[s][tx * 4];
            float xa[4] = {xr.x, xr.y, xr.z, xr.w};
            float bb[4] = {br.x, br.y, br.z, br.w};
            #pragma unroll
            for (int a = 0; a < 4; ++a)
                #pragma unroll
                for (int b2 = 0; b2 < 4; ++b2)
                    acc[a][b2] = fmaf(xa[a], bb[b2], acc[a][b2]);
        }
        #pragma unroll
        for (int a = 0; a < 4; ++a)
            #pragma unroll
            for (int b2 = 0; b2 < 4; ++b2)
                g_states[obase + (size_t)(ty * 4 + a) * DS + n0 + tx * 4 + b2] = acc[a][b2];
        __syncthreads();
    }
}

// ---------------- inter-chunk recurrence ----------------
__global__ __launch_bounds__(256) void recur_kernel()
{
    const int bid = blockIdx.x;
    const int bh  = bid >> 5;
    const int eo  = ((bid & 31) << 8) + threadIdx.x;
    const int b = bh >> 5, h = bh & 31;

    float S = 0.f;
    for (int c = 0; c < NC; ++c) {
        float d = g_dchunk[(b * NC + c) * NH + h];
        size_t idx = ((size_t)((b * NC + c) * NH + h)) * (HP * DS) + eo;
        float t = g_states[idx];
        g_states[idx] = S;
        S = fmaf(d, S, t);
    }
}

// ---------------- Y = Y_off + Y_diag (transposed smem, float4 loads) --------
#define YST 68
__global__ __launch_bounds__(256) void y_kernel()
{
    const int c = blockIdx.x, b = blockIdx.y, h = blockIdx.z;
    const int tid = threadIdx.x;
    const int tx = tid & 15, ty = tid >> 4;
    const int rowBase = b * LSEQ + c * CS;

    __shared__ float a_s[CS];
    __shared__ float acum[CS];
    __shared__ float sT1[CS * YST];
    __shared__ float sT2[CS * YST];

    if (tid < CS) a_s[tid] = g_adt[(rowBase + tid) * NH + h];
    __syncthreads();
    if (tid == 0) {
        float s = 0.f;
        #pragma unroll
        for (int i = 0; i < CS; ++i) { s += a_s[i]; acum[i] = s; }
    }
    __syncthreads();

    float acc[4][4];
    #pragma unroll
    for (int a = 0; a < 4; ++a)
        #pragma unroll
        for (int b2 = 0; b2 < 4; ++b2) acc[a][b2] = 0.f;

    const size_t sbase = ((size_t)((b * NC + c) * NH + h)) * (HP * DS);
    for (int n0 = 0; n0 < DS; n0 += 64) {
        for (int t = tid; t < 4096; t += 256) {
            int i = t >> 6, n = t & 63;
            sT1[n * YST + i] = g_xconv[(size_t)(rowBase + i) * CONVD + DIEXP + DS + n0 + n];
            sT2[n * YST + i] = g_states[sbase + (size_t)i * DS + n0 + n];
        }
        __syncthreads();
        for (int n = 0; n < 64; ++n) {
            float4 cr = *(const float4*)&sT1[n * YST + ty * 4];
            float4 sr = *(const float4*)&sT2[n * YST + tx * 4];
            float ca[4] = {cr.x, cr.y, cr.z, cr.w};
            float sa[4] = {sr.x, sr.y, sr.z, sr.w};
            #pragma unroll
            for (int a = 0; a < 4; ++a)
                #pragma unroll
                for (int b2 = 0; b2 < 4; ++b2)
                    acc[a][b2] = fmaf(ca[a], sa[b2], acc[a][b2]);
        }
        __syncthreads();
    }
    #pragma unroll
    for (int a = 0; a < 4; ++a) {
        float ei = expf(acum[ty * 4 + a]);
        #pragma unroll
        for (int b2 = 0; b2 < 4; ++b2) acc[a][b2] *= ei;
    }

    const int cbBase = (b * NC + c) * 4096;
    for (int t = tid; t < 4096; t += 256) {
        int i = t >> 6, jj = t & 63;
        float w = 0.f;
        if (jj <= i) w = g_CB[cbBase + i * 64 + jj] * expf(acum[i] - acum[jj]);
        sT1[jj * YST + i] = w;
        sT2[i * YST + jj] = g_xconv[(size_t)(rowBase + i) * CONVD + h * HP + jj]
                            * g_dt[(rowBase + i) * NH + h];
    }
    __syncthreads();
    for (int j = 0; j < 64; ++j) {
        float4 wr = *(const float4*)&sT1[j * YST + ty * 4];
        float4 xr = *(const float4*)&sT2[j * YST + tx * 4];
        float wa[4] = {wr.x, wr.y, wr.z, wr.w};
        float xa[4] = {xr.x, xr.y, xr.z, xr.w};
        #pragma unroll
        for (int a = 0; a < 4; ++a)
            #pragma unroll
            for (int b2 = 0; b2 < 4; ++b2)
                acc[a][b2] = fmaf(wa[a], xa[b2], acc[a][b2]);
    }

    #pragma unroll
    for (int a = 0; a < 4; ++a)
        #pragma unroll
        for (int b2 = 0; b2 < 4; ++b2)
            g_y[(size_t)(rowBase + ty * 4 + a) * DIEXP + h * HP + tx * 4 + b2]
                = acc[a][b2];
}

// ---------------- gate + LayerNorm (emits tf32-rounded y) ----------------
__global__ __launch_bounds__(256) void gatenorm_kernel(
    const float* __restrict__ norm_w, const float* __restrict__ norm_b)
{
    const int r = blockIdx.x;
    const int tid = threadIdx.x;
    __shared__ float red[256];

    float v[8];
    float lsum = 0.f;
    #pragma unroll
    for (int e = 0; e < 8; ++e) {
        int col = e * 256 + tid;
        float z  = g_zxbcdt[(size_t)r * DPROJ + col];
        float yv = g_y[(size_t)r * DIEXP + col];
        float val = yv * (z / (1.f + expf(-z)));
        v[e] = val;
        lsum += val;
    }
    red[tid] = lsum;
    __syncthreads();
    for (int o = 128; o > 0; o >>= 1) {
        if (tid < o) red[tid] += red[tid + o];
        __syncthreads();
    }
    float mu = red[0] / (float)DIEXP;
    __syncthreads();

    float ls2 = 0.f;
    #pragma unroll
    for (int e = 0; e < 8; ++e) { float d = v[e] - mu; ls2 = fmaf(d, d, ls2); }
    red[tid] = ls2;
    __syncthreads();
    for (int o = 128; o > 0; o >>= 1) {
        if (tid < o) red[tid] += red[tid + o];
        __syncthreads();
    }
    float rstd = rsqrtf(red[0] / (float)DIEXP + 1e-5f);

    #pragma unroll
    for (int e = 0; e < 8; ++e) {
        int col = e * 256 + tid;
        g_y[(size_t)r * DIEXP + col] =
            tf32r((v[e] - mu) * rstd * norm_w[col] + norm_b[col]);
    }
}

// ---------------- launch ----------------
extern "C" void kernel_launch(void* const* d_in, const int* in_sizes, int n_in,
                              void* d_out, int out_size)
{
    const float* u       = (const float*)d_in[0];
    const float* W_in    = (const float*)d_in[1];
    const float* conv_w  = (const float*)d_in[2];
    const float* conv_b  = (const float*)d_in[3];
    const float* dt_bias = (const float*)d_in[4];
    const float* A_log   = (const float*)d_in[5];
    const float* norm_w  = (const float*)d_in[6];
    const float* norm_b  = (const float*)d_in[7];
    const float* W_out   = (const float*)d_in[8];
    float* out = (float*)d_out;

    float *zx = nullptr, *yb = nullptr, *sc = nullptr, *wt = nullptr;
    cudaGetSymbolAddress((void**)&zx, g_zxbcdt);
    cudaGetSymbolAddress((void**)&yb, g_y);
    cudaGetSymbolAddress((void**)&sc, g_states);
    cudaGetSymbolAddress((void**)&wt, g_WT);

    const int GEMM_SMEM = 2 * GSTG * STG_BYTES;    // 110592 B
    cudaFuncSetAttribute(gemm_mma_kernel,
                         cudaFuncAttributeMaxDynamicSharedMemorySize, GEMM_SMEM);

    // 0) pre-round u; transpose+round weights to K-major
    round_u_kernel<<<(ROWS * DMODEL / 4 + 255) / 256, 256>>>(u, sc);
    transpose_round_kernel<<<dim3((DPROJ + 31) / 32, (DMODEL + 31) / 32), 256>>>(
        W_in, wt, DMODEL, DPROJ);
    transpose_round_kernel<<<dim3((DMODEL + 31) / 32, (DIEXP + 31) / 32), 256>>>(
        W_out, wt + (size_t)DPROJ * DMODEL, DIEXP, DMODEL);

    // 1) zxbcdt = u @ W_in
    gemm_mma_kernel<<<dim3((DPROJ + 127) / 128, ROWS / 128), 256, GEMM_SMEM>>>(
        sc, wt, zx, ROWS, DPROJ, DMODEL);
    // 2) causal dwconv + silu (float4)
    conv_silu_kernel<<<(ROWS * (CONVD / 4) + 255) / 256, 256>>>(conv_w, conv_b);
    // 3) dt / A*dt
    dt_kernel<<<(ROWS * NH + 255) / 256, 256>>>(dt_bias, A_log);
    // 4) CB gram
    cb_kernel<<<BSZ * NC, 256>>>();
    // 5) per-chunk states
    states_kernel<<<dim3(NC, BSZ, NH), 256>>>();
    // 6) inter-chunk recurrence
    recur_kernel<<<BSZ * NH * 32, 256>>>();
    // 7) Y
    y_kernel<<<dim3(NC, BSZ, NH), 256>>>();
    // 8) gate + layernorm (emits tf32-rounded y)
    gatenorm_kernel<<<ROWS, 256>>>(norm_w, norm_b);
    // 9) out = y @ W_out
    gemm_mma_kernel<<<dim3(DMODEL / 128, ROWS / 128), 256, GEMM_SMEM>>>(
        yb, wt + (size_t)DPROJ * DMODEL, out, ROWS, DMODEL, DIEXP);
}

// round 8
// speedup vs baseline: 3.1505x; 1.2567x over previous
#include <cuda_runtime.h>
#include <math.h>
#include <stdint.h>

// ---------------- problem constants ----------------
#define BSZ    2
#define LSEQ   4096
#define DMODEL 1024
#define DIEXP  2048
#define NH     32
#define HP     64
#define DS     128
#define CS     64
#define NC     64
#define DPROJ  4384
#define CONVD  2304
#define ROWS   8192
#define NBCH   (BSZ * NC * NH)          // 4096

// ---------------- device scratch ----------------
__device__ float g_zxbcdt[(size_t)ROWS * DPROJ];
__device__ float g_xt    [(size_t)NBCH * HP * CS];        // x^T per (b,c,h): [p][s], fp32
__device__ float g_bc    [(size_t)ROWS * 256];            // [row][B(128)|C(128)], tf32-rounded
__device__ float g_bt    [(size_t)BSZ * NC * DS * CS];    // B^T per (b,c): [n][s], tf32-rounded
__device__ float g_acum  [NBCH * CS];
__device__ float g_dt    [ROWS * NH];
__device__ float g_adt   [ROWS * NH];
__device__ float g_CB    [BSZ * NC * CS * CS];            // tf32-valued (mma output fp32)
__device__ float g_states[(size_t)NBCH * HP * DS];        // head reused as rounded-u scratch
__device__ float g_dchunk[NBCH];
__device__ float g_y     [(size_t)ROWS * DIEXP];
__device__ float g_WT    [(size_t)DPROJ * DMODEL + (size_t)DMODEL * DIEXP];

// ---------------- helpers ----------------
__device__ __forceinline__ uint32_t f2tf32(float x) {
    uint32_t r;
    asm("cvt.rna.tf32.f32 %0, %1;" : "=r"(r) : "f"(x));
    return r;
}
__device__ __forceinline__ float tf32r(float x) { return __uint_as_float(f2tf32(x)); }

__device__ __forceinline__ uint32_t smem_u32(const void* p) {
    uint32_t a;
    asm("{ .reg .u64 t; cvta.to.shared.u64 t, %1; cvt.u32.u64 %0, t; }" : "=r"(a) : "l"(p));
    return a;
}
__device__ __forceinline__ void cp_async16(uint32_t dst, const void* src) {
    asm volatile("cp.async.cg.shared.global [%0], [%1], 16;" :: "r"(dst), "l"(src) : "memory");
}
#define MMA_TF32(acc, af, bf)                                               \
    asm volatile(                                                           \
        "mma.sync.aligned.m16n8k8.row.col.f32.tf32.tf32.f32 "               \
        "{%0,%1,%2,%3}, {%4,%5,%6,%7}, {%8,%9}, {%0,%1,%2,%3};\n"           \
        : "+f"((acc)[0]), "+f"((acc)[1]), "+f"((acc)[2]), "+f"((acc)[3])    \
        : "r"((af)[0]), "r"((af)[1]), "r"((af)[2]), "r"((af)[3]),           \
          "r"((bf)[0]), "r"((bf)[1]))

// =====================================================================
// tf32 mma.sync dense GEMM (identical to R7 proven version)
// =====================================================================
#define GSTG 3
#define ROWB 144
#define STG_BYTES (128 * ROWB)

__global__ __launch_bounds__(256) void gemm_mma_kernel(
    const float* __restrict__ A, const float* __restrict__ BT,
    float* __restrict__ C, int M, int N, int K)
{
    extern __shared__ char sm[];
    const uint32_t sb = smem_u32(sm);
    const int tid  = threadIdx.x;
    const int wid  = tid >> 5, lane = tid & 31;
    const int gid  = lane >> 2, tig = lane & 3;
    const int wm   = wid >> 1,  wn  = wid & 1;
    const int mBase = blockIdx.y * 128, nBase = blockIdx.x * 128;

    float acc[2][8][4];
    #pragma unroll
    for (int t = 0; t < 2; ++t)
        #pragma unroll
        for (int j = 0; j < 8; ++j)
            #pragma unroll
            for (int e = 0; e < 4; ++e) acc[t][j][e] = 0.f;

    const int KT = K >> 5;
    const int lrow = tid >> 3, lc16 = tid & 7;
    const int aOff = (wm * 32 + gid) * ROWB + tig * 4;
    const int bOff = (wn * 64 + gid) * ROWB + tig * 4;

    auto load_stage = [&](int kt, int s) {
        const int k0 = kt << 5;
        const uint32_t ab = sb + s * STG_BYTES;
        const uint32_t bb = sb + GSTG * STG_BYTES + s * STG_BYTES;
        #pragma unroll
        for (int i = 0; i < 4; ++i) {
            int row = lrow + i * 32;
            cp_async16(ab + row * ROWB + lc16 * 16,
                       A + (size_t)(mBase + row) * K + k0 + lc16 * 4);
        }
        #pragma unroll
        for (int i = 0; i < 4; ++i) {
            int row = lrow + i * 32;
            int nr = nBase + row; if (nr >= N) nr = N - 1;
            cp_async16(bb + row * ROWB + lc16 * 16,
                       BT + (size_t)nr * K + k0 + lc16 * 4);
        }
        asm volatile("cp.async.commit_group;" ::: "memory");
    };

    load_stage(0, 0);
    if (KT > 1) load_stage(1, 1);

    for (int kt = 0; kt < KT; ++kt) {
        const int s = kt % GSTG;
        asm volatile("cp.async.wait_group 1;" ::: "memory");
        __syncthreads();

        const char* As = sm + s * STG_BYTES + aOff;
        const char* Bs = sm + GSTG * STG_BYTES + s * STG_BYTES + bOff;

        #pragma unroll
        for (int ks = 0; ks < 4; ++ks) {
            const int kb = ks * 32;
            uint32_t af[2][4];
            #pragma unroll
            for (int t = 0; t < 2; ++t) {
                const char* a = As + t * (16 * ROWB) + kb;
                af[t][0] = *(const uint32_t*)(a);
                af[t][1] = *(const uint32_t*)(a + 8 * ROWB);
                af[t][2] = *(const uint32_t*)(a + 16);
                af[t][3] = *(const uint32_t*)(a + 8 * ROWB + 16);
            }
            uint32_t bf[8][2];
            #pragma unroll
            for (int j = 0; j < 8; ++j) {
                const char* bp = Bs + j * (8 * ROWB) + kb;
                bf[j][0] = *(const uint32_t*)(bp);
                bf[j][1] = *(const uint32_t*)(bp + 16);
            }
            #pragma unroll
            for (int t = 0; t < 2; ++t)
                #pragma unroll
                for (int j = 0; j < 8; ++j)
                    MMA_TF32(acc[t][j], af[t], bf[j]);
        }
        if (kt + 2 < KT) load_stage(kt + 2, (kt + 2) % GSTG);
    }

    #pragma unroll
    for (int t = 0; t < 2; ++t) {
        int r0 = mBase + wm * 32 + t * 16 + gid;
        #pragma unroll
        for (int j = 0; j < 8; ++j) {
            int c0 = nBase + wn * 64 + j * 8 + tig * 2;
            if (c0 + 1 < N) {
                *(float2*)&C[(size_t)r0 * N + c0]       = make_float2(acc[t][j][0], acc[t][j][1]);
                *(float2*)&C[(size_t)(r0 + 8) * N + c0] = make_float2(acc[t][j][2], acc[t][j][3]);
            } else if (c0 < N) {
                C[(size_t)r0 * N + c0]       = acc[t][j][0];
                C[(size_t)(r0 + 8) * N + c0] = acc[t][j][2];
            }
        }
    }
}

// ---------------- pre-rounding / weight transpose ----------------
__global__ __launch_bounds__(256) void round_u_kernel(const float* __restrict__ u, float* __restrict__ o)
{
    int idx = blockIdx.x * 256 + threadIdx.x;
    if (idx < ROWS * DMODEL / 4) {
        float4 v = ((const float4*)u)[idx];
        v.x = tf32r(v.x); v.y = tf32r(v.y); v.z = tf32r(v.z); v.w = tf32r(v.w);
        ((float4*)o)[idx] = v;
    }
}

__global__ __launch_bounds__(256) void transpose_round_kernel(
    const float* __restrict__ W, float* __restrict__ WT, int K, int N)
{
    __shared__ float tile[32][33];
    const int bx = blockIdx.x * 32, by = blockIdx.y * 32;
    const int x = threadIdx.x & 31, y = threadIdx.x >> 5;
    #pragma unroll
    for (int i = 0; i < 32; i += 8) {
        int k = by + y + i, n = bx + x;
        tile[y + i][x] = (k < K && n < N) ? W[(size_t)k * N + n] : 0.f;
    }
    __syncthreads();
    #pragma unroll
    for (int i = 0; i < 32; i += 8) {
        int n = bx + y + i, k = by + x;
        if (n < N && k < K) WT[(size_t)n * K + k] = tf32r(tile[x][y + i]);
    }
}

// ---------------- conv + SiLU -> mma-ready layouts ----------------
// One thread computes 4 consecutive seq positions of one channel (sliding window).
// x channels  -> g_xt[(b,c,h)][p][s]  (fp32, transposed)
// B channels  -> g_bc[row][n] (tf32) AND g_bt[(b,c)][n][s] (tf32, transposed)
// C channels  -> g_bc[row][128+n] (tf32)
__global__ __launch_bounds__(256) void conv_silu_kernel(
    const float* __restrict__ conv_w, const float* __restrict__ conv_b)
{
    int idx = blockIdx.x * 256 + threadIdx.x;
    if (idx >= CONVD * (ROWS / 4)) return;
    const int ch = idx % CONVD;
    const int r4 = idx / CONVD;
    const int r0 = r4 * 4;
    const int b  = r0 >> 12;
    const int l0 = r0 & (LSEQ - 1);

    const float w0 = conv_w[ch * 4 + 0], w1 = conv_w[ch * 4 + 1];
    const float w2 = conv_w[ch * 4 + 2], w3 = conv_w[ch * 4 + 3];
    const float bias = conv_b[ch];

    float in[7];
    #pragma unroll
    for (int i = 0; i < 7; ++i) {
        int l = l0 - 3 + i;
        in[i] = (l >= 0) ? g_zxbcdt[(size_t)(r0 - 3 + i) * DPROJ + DIEXP + ch] : 0.f;
    }
    float o[4];
    #pragma unroll
    for (int k = 0; k < 4; ++k) {
        float a = bias;
        a = fmaf(in[k],     w0, a);
        a = fmaf(in[k + 1], w1, a);
        a = fmaf(in[k + 2], w2, a);
        a = fmaf(in[k + 3], w3, a);
        o[k] = a / (1.f + expf(-a));
    }

    const int c  = l0 >> 6;
    const int s0 = l0 & 63;

    if (ch < DIEXP) {
        const int h = ch >> 6, p = ch & 63;
        const size_t base = (((size_t)((b * NC + c) * NH + h)) * HP + p) * CS + s0;
        *(float4*)&g_xt[base] = make_float4(o[0], o[1], o[2], o[3]);
    } else {
        const int cc = ch - DIEXP;   // 0..255
        #pragma unroll
        for (int k = 0; k < 4; ++k)
            g_bc[(size_t)(r0 + k) * 256 + cc] = tf32r(o[k]);
        if (cc < DS) {
            const size_t base = ((size_t)(b * NC + c) * DS + cc) * CS + s0;
            *(float4*)&g_bt[base] = make_float4(tf32r(o[0]), tf32r(o[1]), tf32r(o[2]), tf32r(o[3]));
        }
    }
}

// ---------------- dt / A*dt ----------------
__global__ __launch_bounds__(256) void dt_kernel(
    const float* __restrict__ dt_bias, const float* __restrict__ A_log)
{
    int idx = blockIdx.x * 256 + threadIdx.x;
    if (idx >= ROWS * NH) return;
    int r = idx >> 5;
    int h = idx & 31;
    float x = g_zxbcdt[(size_t)r * DPROJ + (DPROJ - NH) + h] + dt_bias[h];
    float sp = (x > 20.f) ? x : log1pf(expf(x));
    g_dt[idx]  = sp;
    g_adt[idx] = -expf(A_log[h]) * sp;
}

// ---------------- per-(b,c,h) cumsum of adt ----------------
__global__ __launch_bounds__(256) void acum_kernel()
{
    int bch = blockIdx.x * 256 + threadIdx.x;
    if (bch >= NBCH) return;
    int h = bch & 31;
    int c = (bch >> 5) & 63;
    int b = bch >> 11;
    int rowBase = b * LSEQ + c * CS;
    float a = 0.f;
    #pragma unroll 8
    for (int s = 0; s < CS; ++s) {
        a += g_adt[(rowBase + s) * NH + h];
        g_acum[bch * CS + s] = a;
    }
    g_dchunk[bch] = expf(a);
}

// ---------------- CB gram via mma: CB[i][j] = sum_n C[i,n]*B[j,n] ----------
__global__ __launch_bounds__(256) void cb_kernel()
{
    extern __shared__ float dsm[];
    float* As = dsm;                 // 64 x 132  (C)
    float* Bs = dsm + 64 * 132;      // 64 x 132  (B)
    const int bc = blockIdx.x;
    const int rowBase = bc * CS;
    const int tid = threadIdx.x;
    const int wid = tid >> 5, lane = tid & 31;
    const int gid = lane >> 2, tig = lane & 3;
    const int wm = wid >> 2, wn = wid & 3;

    for (int t = tid; t < 2048; t += 256) {
        int i = t >> 5, n4 = (t & 31) * 4;
        const float4 cv = *(const float4*)&g_bc[(size_t)(rowBase + i) * 256 + 128 + n4];
        const float4 bv = *(const float4*)&g_bc[(size_t)(rowBase + i) * 256 + n4];
        *(float4*)&As[i * 132 + n4] = cv;
        *(float4*)&Bs[i * 132 + n4] = bv;
    }
    __syncthreads();

    float acc[2][2][4];
    #pragma unroll
    for (int t = 0; t < 2; ++t)
        #pragma unroll
        for (int j = 0; j < 2; ++j)
            #pragma unroll
            for (int e = 0; e < 4; ++e) acc[t][j][e] = 0.f;

    const float* Aw = As + (wm * 32 + gid) * 132 + tig;
    const float* Bw = Bs + (wn * 16 + gid) * 132 + tig;
    #pragma unroll
    for (int ks = 0; ks < 16; ++ks) {
        const int ko = ks * 8;
        uint32_t af[2][4], bf[2][2];
        #pragma unroll
        for (int t = 0; t < 2; ++t) {
            const float* a = Aw + t * (16 * 132) + ko;
            af[t][0] = __float_as_uint(a[0]);
            af[t][1] = __float_as_uint(a[8 * 132]);
            af[t][2] = __float_as_uint(a[4]);
            af[t][3] = __float_as_uint(a[8 * 132 + 4]);
        }
        #pragma unroll
        for (int j = 0; j < 2; ++j) {
            const float* bp = Bw + j * (8 * 132) + ko;
            bf[j][0] = __float_as_uint(bp[0]);
            bf[j][1] = __float_as_uint(bp[4]);
        }
        #pragma unroll
        for (int t = 0; t < 2; ++t)
            #pragma unroll
            for (int j = 0; j < 2; ++j)
                MMA_TF32(acc[t][j], af[t], bf[j]);
    }

    #pragma unroll
    for (int t = 0; t < 2; ++t) {
        int i0 = wm * 32 + t * 16 + gid;
        #pragma unroll
        for (int j = 0; j < 2; ++j) {
            int j0 = wn * 16 + j * 8 + tig * 2;
            *(float2*)&g_CB[bc * 4096 + i0 * 64 + j0]       = make_float2(acc[t][j][0], acc[t][j][1]);
            *(float2*)&g_CB[bc * 4096 + (i0 + 8) * 64 + j0] = make_float2(acc[t][j][2], acc[t][j][3]);
        }
    }
}

// ---------------- states via mma: S[p][n] = sum_s xw[s,p]*B[s,n] ----------
__global__ __launch_bounds__(256) void states_kernel()
{
    extern __shared__ float dsm[];
    float* wv = dsm;                  // 64
    float* As = dsm + 128;            // 64 x 68   xw^T[p][s]
    float* Bs = As + 64 * 68;         // 128 x 68  B^T[n][s]
    const int c = blockIdx.x, b = blockIdx.y, h = blockIdx.z;
    const int bch = (b * NC + c) * NH + h;
    const int rowBase = b * LSEQ + c * CS;
    const int tid = threadIdx.x;
    const int wid = tid >> 5, lane = tid & 31;
    const int gid = lane >> 2, tig = lane & 3;
    const int wm = wid >> 2, wn = wid & 3;

    if (tid < CS) {
        float aend = g_acum[bch * CS + CS - 1];
        float ac   = g_acum[bch * CS + tid];
        wv[tid] = g_dt[(rowBase + tid) * NH + h] * expf(aend - ac);
    }
    __syncthreads();

    // A: xw^T[p][s] = xt[p][s] * wv[s]   (round after scale)
    const float* xt = &g_xt[(size_t)bch * (HP * CS)];
    for (int t = tid; t < 1024; t += 256) {
        int p = t >> 4, s4 = (t & 15) * 4;
        float4 v = *(const float4*)&xt[p * CS + s4];
        v.x = tf32r(v.x * wv[s4 + 0]);
        v.y = tf32r(v.y * wv[s4 + 1]);
        v.z = tf32r(v.z * wv[s4 + 2]);
        v.w = tf32r(v.w * wv[s4 + 3]);
        *(float4*)&As[p * 68 + s4] = v;
    }
    // B: copy B^T (already rounded)
    const float* bt = &g_bt[(size_t)(b * NC + c) * (DS * CS)];
    for (int t = tid; t < 2048; t += 256) {
        int n = t >> 4, s4 = (t & 15) * 4;
        *(float4*)&Bs[n * 68 + s4] = *(const float4*)&bt[n * CS + s4];
    }
    __syncthreads();

    float acc[2][4][4];
    #pragma unroll
    for (int t = 0; t < 2; ++t)
        #pragma unroll
        for (int j = 0; j < 4; ++j)
            #pragma unroll
            for (int e = 0; e < 4; ++e) acc[t][j][e] = 0.f;

    const float* Aw = As + (wm * 32 + gid) * 68 + tig;
    const float* Bw = Bs + (wn * 32 + gid) * 68 + tig;
    #pragma unroll
    for (int ks = 0; ks < 8; ++ks) {
        const int ko = ks * 8;
        uint32_t af[2][4], bf[4][2];
        #pragma unroll
        for (int t = 0; t < 2; ++t) {
            const float* a = Aw + t * (16 * 68) + ko;
            af[t][0] = __float_as_uint(a[0]);
            af[t][1] = __float_as_uint(a[8 * 68]);
            af[t][2] = __float_as_uint(a[4]);
            af[t][3] = __float_as_uint(a[8 * 68 + 4]);
        }
        #pragma unroll
        for (int j = 0; j < 4; ++j) {
            const float* bp = Bw + j * (8 * 68) + ko;
            bf[j][0] = __float_as_uint(bp[0]);
            bf[j][1] = __float_as_uint(bp[4]);
        }
        #pragma unroll
        for (int t = 0; t < 2; ++t)
            #pragma unroll
            for (int j = 0; j < 4; ++j)
                MMA_TF32(acc[t][j], af[t], bf[j]);
    }

    float* S = &g_states[(size_t)bch * (HP * DS)];
    #pragma unroll
    for (int t = 0; t < 2; ++t) {
        int p0 = wm * 32 + t * 16 + gid;
        #pragma unroll
        for (int j = 0; j < 4; ++j) {
            int n0 = wn * 32 + j * 8 + tig * 2;
            *(float2*)&S[p0 * DS + n0]       = make_float2(acc[t][j][0], acc[t][j][1]);
            *(float2*)&S[(p0 + 8) * DS + n0] = make_float2(acc[t][j][2], acc[t][j][3]);
        }
    }
}

// ---------------- inter-chunk recurrence ----------------
__global__ __launch_bounds__(256) void recur_kernel()
{
    const int bid = blockIdx.x;
    const int bh  = bid >> 5;
    const int eo  = ((bid & 31) << 8) + threadIdx.x;
    const int b = bh >> 5, h = bh & 31;

    float S = 0.f;
    for (int c = 0; c < NC; ++c) {
        int bch = (b * NC + c) * NH + h;
        float d = g_dchunk[bch];
        size_t idx = (size_t)bch * (HP * DS) + eo;
        float t = g_states[idx];
        g_states[idx] = S;
        S = fmaf(d, S, t);
    }
}

// ---------------- Y via mma: Yoff (K=128) + Yd (K=64) ----------------
__global__ __launch_bounds__(256) void y_kernel()
{
    extern __shared__ float dsm[];
    float* avec = dsm;                 // 64
    float* eac  = dsm + 64;            // 64
    float* dtv  = dsm + 128;           // 64
    float* As   = dsm + 256;           // 64x132 (A) / 64x68 (B-phase)
    float* Bs   = As + 64 * 132;       // 64x132 / 64x68
    const int c = blockIdx.x, b = blockIdx.y, h = blockIdx.z;
    const int bch = (b * NC + c) * NH + h;
    const int rowBase = b * LSEQ + c * CS;
    const int tid = threadIdx.x;
    const int wid = tid >> 5, lane = tid & 31;
    const int gid = lane >> 2, tig = lane & 3;
    const int wm = wid >> 2, wn = wid & 3;

    if (tid < CS) {
        float ac = g_acum[bch * CS + tid];
        avec[tid] = ac;
        eac[tid]  = expf(ac);
        dtv[tid]  = g_dt[(rowBase + tid) * NH + h];
    }
    __syncthreads();

    // Phase A staging: A[i][n] = C[i][n]*eac[i], B[p][n] = Sin[p][n]
    const float* Sin = &g_states[(size_t)bch * (HP * DS)];
    for (int t = tid; t < 2048; t += 256) {
        int i = t >> 5, n4 = (t & 31) * 4;
        float e = eac[i];
        float4 cv = *(const float4*)&g_bc[(size_t)(rowBase + i) * 256 + 128 + n4];
        cv.x = tf32r(cv.x * e); cv.y = tf32r(cv.y * e);
        cv.z = tf32r(cv.z * e); cv.w = tf32r(cv.w * e);
        *(float4*)&As[i * 132 + n4] = cv;
        float4 sv = *(const float4*)&Sin[i * DS + n4];
        sv.x = tf32r(sv.x); sv.y = tf32r(sv.y);
        sv.z = tf32r(sv.z); sv.w = tf32r(sv.w);
        *(float4*)&Bs[i * 132 + n4] = sv;
    }
    __syncthreads();

    float acc[2][2][4];
    #pragma unroll
    for (int t = 0; t < 2; ++t)
        #pragma unroll
        for (int j = 0; j < 2; ++j)
            #pragma unroll
            for (int e = 0; e < 4; ++e) acc[t][j][e] = 0.f;

    {
        const float* Aw = As + (wm * 32 + gid) * 132 + tig;
        const float* Bw = Bs + (wn * 16 + gid) * 132 + tig;
        #pragma unroll
        for (int ks = 0; ks < 16; ++ks) {
            const int ko = ks * 8;
            uint32_t af[2][4], bf[2][2];
            #pragma unroll
            for (int t = 0; t < 2; ++t) {
                const float* a = Aw + t * (16 * 132) + ko;
                af[t][0] = __float_as_uint(a[0]);
                af[t][1] = __float_as_uint(a[8 * 132]);
                af[t][2] = __float_as_uint(a[4]);
                af[t][3] = __float_as_uint(a[8 * 132 + 4]);
            }
            #pragma unroll
            for (int j = 0; j < 2; ++j) {
                const float* bp = Bw + j * (8 * 132) + ko;
                bf[j][0] = __float_as_uint(bp[0]);
                bf[j][1] = __float_as_uint(bp[4]);
            }
            #pragma unroll
            for (int t = 0; t < 2; ++t)
                #pragma unroll
                for (int j = 0; j < 2; ++j)
                    MMA_TF32(acc[t][j], af[t], bf[j]);
        }
    }
    __syncthreads();

    // Phase B staging: A[i][j] = W (masked decay * CB), B[p][j] = xt[p][j]*dt[j]
    const int cbBase = (b * NC + c) * 4096;
    for (int t = tid; t < 4096; t += 256) {
        int i = t >> 6, jj = t & 63;
        float w = 0.f;
        if (jj <= i) w = tf32r(g_CB[cbBase + i * 64 + jj] * expf(avec[i] - avec[jj]));
        As[i * 68 + jj] = w;
    }
    const float* xt = &g_xt[(size_t)bch * (HP * CS)];
    for (int t = tid; t < 1024; t += 256) {
        int p = t >> 4, j4 = (t & 15) * 4;
        float4 v = *(const float4*)&xt[p * CS + j4];
        v.x = tf32r(v.x * dtv[j4 + 0]);
        v.y = tf32r(v.y * dtv[j4 + 1]);
        v.z = tf32r(v.z * dtv[j4 + 2]);
        v.w = tf32r(v.w * dtv[j4 + 3]);
        *(float4*)&Bs[p * 68 + j4] = v;
    }
    __syncthreads();

    {
        const float* Aw = As + (wm * 32 + gid) * 68 + tig;
        const float* Bw = Bs + (wn * 16 + gid) * 68 + tig;
        #pragma unroll
        for (int ks = 0; ks < 8; ++ks) {
            const int ko = ks * 8;
            uint32_t af[2][4], bf[2][2];
            #pragma unroll
            for (int t = 0; t < 2; ++t) {
                const float* a = Aw + t * (16 * 68) + ko;
                af[t][0] = __float_as_uint(a[0]);
                af[t][1] = __float_as_uint(a[8 * 68]);
                af[t][2] = __float_as_uint(a[4]);
                af[t][3] = __float_as_uint(a[8 * 68 + 4]);
            }
            #pragma unroll
            for (int j = 0; j < 2; ++j) {
                const float* bp = Bw + j * (8 * 68) + ko;
                bf[j][0] = __float_as_uint(bp[0]);
                bf[j][1] = __float_as_uint(bp[4]);
            }
            #pragma unroll
            for (int t = 0; t < 2; ++t)
                #pragma unroll
                for (int j = 0; j < 2; ++j)
                    MMA_TF32(acc[t][j], af[t], bf[j]);
        }
    }

    #pragma unroll
    for (int t = 0; t < 2; ++t) {
        int i0 = wm * 32 + t * 16 + gid;
        #pragma unroll
        for (int j = 0; j < 2; ++j) {
            int col = h * HP + wn * 16 + j * 8 + tig * 2;
            *(float2*)&g_y[(size_t)(rowBase + i0) * DIEXP + col]
                = make_float2(acc[t][j][0], acc[t][j][1]);
            *(float2*)&g_y[(size_t)(rowBase + i0 + 8) * DIEXP + col]
                = make_float2(acc[t][j][2], acc[t][j][3]);
        }
    }
}

// ---------------- gate + LayerNorm (emits tf32-rounded y) ----------------
__global__ __launch_bounds__(256) void gatenorm_kernel(
    const float* __restrict__ norm_w, const float* __restrict__ norm_b)
{
    const int r = blockIdx.x;
    const int tid = threadIdx.x;
    __shared__ float red[256];

    float v[8];
    float lsum = 0.f;
    #pragma unroll
    for (int e = 0; e < 8; ++e) {
        int col = e * 256 + tid;
        float z  = g_zxbcdt[(size_t)r * DPROJ + col];
        float yv = g_y[(size_t)r * DIEXP + col];
        float val = yv * (z / (1.f + expf(-z)));
        v[e] = val;
        lsum += val;
    }
    red[tid] = lsum;
    __syncthreads();
    for (int o = 128; o > 0; o >>= 1) {
        if (tid < o) red[tid] += red[tid + o];
        __syncthreads();
    }
    float mu = red[0] / (float)DIEXP;
    __syncthreads();

    float ls2 = 0.f;
    #pragma unroll
    for (int e = 0; e < 8; ++e) { float d = v[e] - mu; ls2 = fmaf(d, d, ls2); }
    red[tid] = ls2;
    __syncthreads();
    for (int o = 128; o > 0; o >>= 1) {
        if (tid < o) red[tid] += red[tid + o];
        __syncthreads();
    }
    float rstd = rsqrtf(red[0] / (float)DIEXP + 1e-5f);

    #pragma unroll
    for (int e = 0; e < 8; ++e) {
        int col = e * 256 + tid;
        g_y[(size_t)r * DIEXP + col] =
            tf32r((v[e] - mu) * rstd * norm_w[col] + norm_b[col]);
    }
}

// ---------------- launch ----------------
extern "C" void kernel_launch(void* const* d_in, const int* in_sizes, int n_in,
                              void* d_out, int out_size)
{
    const float* u       = (const float*)d_in[0];
    const float* W_in    = (const float*)d_in[1];
    const float* conv_w  = (const float*)d_in[2];
    const float* conv_b  = (const float*)d_in[3];
    const float* dt_bias = (const float*)d_in[4];
    const float* A_log   = (const float*)d_in[5];
    const float* norm_w  = (const float*)d_in[6];
    const float* norm_b  = (const float*)d_in[7];
    const float* W_out   = (const float*)d_in[8];
    float* out = (float*)d_out;

    float *zx = nullptr, *yb = nullptr, *sc = nullptr, *wt = nullptr;
    cudaGetSymbolAddress((void**)&zx, g_zxbcdt);
    cudaGetSymbolAddress((void**)&yb, g_y);
    cudaGetSymbolAddress((void**)&sc, g_states);
    cudaGetSymbolAddress((void**)&wt, g_WT);

    const int GEMM_SMEM   = 2 * GSTG * STG_BYTES;                  // 110592
    const int CB_SMEM     = 2 * 64 * 132 * 4;                      // 67584
    const int STATES_SMEM = (128 + 64 * 68 + 128 * 68) * 4;        // 52736
    const int Y_SMEM      = (256 + 2 * 64 * 132) * 4;              // 68608
    cudaFuncSetAttribute(gemm_mma_kernel, cudaFuncAttributeMaxDynamicSharedMemorySize, GEMM_SMEM);
    cudaFuncSetAttribute(cb_kernel,       cudaFuncAttributeMaxDynamicSharedMemorySize, CB_SMEM);
    cudaFuncSetAttribute(states_kernel,   cudaFuncAttributeMaxDynamicSharedMemorySize, STATES_SMEM);
    cudaFuncSetAttribute(y_kernel,        cudaFuncAttributeMaxDynamicSharedMemorySize, Y_SMEM);

    // 0) pre-round u; transpose+round weights
    round_u_kernel<<<(ROWS * DMODEL / 4 + 255) / 256, 256>>>(u, sc);
    transpose_round_kernel<<<dim3((DPROJ + 31) / 32, (DMODEL + 31) / 32), 256>>>(
        W_in, wt, DMODEL, DPROJ);
    transpose_round_kernel<<<dim3((DMODEL + 31) / 32, (DIEXP + 31) / 32), 256>>>(
        W_out, wt + (size_t)DPROJ * DMODEL, DIEXP, DMODEL);

    // 1) zxbcdt = u @ W_in
    gemm_mma_kernel<<<dim3((DPROJ + 127) / 128, ROWS / 128), 256, GEMM_SMEM>>>(
        sc, wt, zx, ROWS, DPROJ, DMODEL);
    // 2) conv + silu -> mma-ready layouts
    conv_silu_kernel<<<(CONVD * (ROWS / 4) + 255) / 256, 256>>>(conv_w, conv_b);
    // 3) dt / A*dt ; cumulative sums
    dt_kernel<<<(ROWS * NH + 255) / 256, 256>>>(dt_bias, A_log);
    acum_kernel<<<(NBCH + 255) / 256, 256>>>();
    // 4) CB gram (mma)
    cb_kernel<<<BSZ * NC, 256, CB_SMEM>>>();
    // 5) per-chunk states (mma)
    states_kernel<<<dim3(NC, BSZ, NH), 256, STATES_SMEM>>>();
    // 6) inter-chunk recurrence
    recur_kernel<<<BSZ * NH * 32, 256>>>();
    // 7) Y (mma)
    y_kernel<<<dim3(NC, BSZ, NH), 256, Y_SMEM>>>();
    // 8) gate + layernorm
    gatenorm_kernel<<<ROWS, 256>>>(norm_w, norm_b);
    // 9) out = y @ W_out
    gemm_mma_kernel<<<dim3(DMODEL / 128, ROWS / 128), 256, GEMM_SMEM>>>(
        yb, wt + (size_t)DPROJ * DMODEL, out, ROWS, DMODEL, DIEXP);
}